// round 1
// baseline (speedup 1.0000x reference)
#include <cuda_runtime.h>
#include <cuda_bf16.h>
#include <math.h>

#define B_  64
#define T_  256
#define C_  256
#define H_  8
#define HS_ 32
#define L_  6
#define V_  96
#define BT_ (B_ * T_)
#define EPS_ 1e-5f

// ---------------- scratch (device globals: allocation-free) ----------------
__device__ float g_x[BT_ * C_];
__device__ float g_q[BT_ * C_];
__device__ float g_k[BT_ * C_];
__device__ float g_v[BT_ * C_];
__device__ float g_att[BT_ * C_];
__device__ float g_tmp[BT_ * C_];
__device__ float g_h[BT_ * C_];
__device__ float g_nll[BT_];

// ---------------- embedding ----------------
__global__ void embed_kernel(const int* __restrict__ idx,
                             const float* __restrict__ tok_emb,
                             const float* __restrict__ pos_emb,
                             float* __restrict__ x) {
    int bt = blockIdx.x;          // 0..BT-1
    int c  = threadIdx.x;         // 0..C-1
    int t  = bt % T_;
    int tok = idx[bt];
    x[bt * C_ + c] = tok_emb[tok * C_ + c] + pos_emb[t * C_ + c];
}

// ---------------- generic tiled fp32 GEMM:  C = A[M,K] @ W[K,N] (+bias)(+relu)
#define BM 64
#define BN 64
#define BK 16
#define TM 4
#define TN 4
__global__ void gemm_kernel(const float* __restrict__ A,
                            const float* __restrict__ W,
                            const float* __restrict__ bias,
                            float* __restrict__ Cout,
                            int M, int N, int K, int relu) {
    __shared__ float As[BK][BM];
    __shared__ float Bs[BK][BN];
    const int tid = threadIdx.x;
    const int tx = tid % 16;      // N direction
    const int ty = tid / 16;      // M direction
    const int row0 = blockIdx.y * BM;
    const int col0 = blockIdx.x * BN;

    float acc[TM][TN];
#pragma unroll
    for (int i = 0; i < TM; i++)
#pragma unroll
        for (int j = 0; j < TN; j++) acc[i][j] = 0.f;

    for (int k0 = 0; k0 < K; k0 += BK) {
        // load A tile (BM x BK) transposed into As[k][m]
#pragma unroll
        for (int i = tid; i < BM * BK; i += 256) {
            int m = i / BK, k = i % BK;
            As[k][m] = A[(size_t)(row0 + m) * K + k0 + k];
        }
        // load W tile (BK x BN)
#pragma unroll
        for (int i = tid; i < BK * BN; i += 256) {
            int k = i / BN, n = i % BN;
            int col = col0 + n;
            Bs[k][n] = (col < N) ? W[(size_t)(k0 + k) * N + col] : 0.f;
        }
        __syncthreads();
#pragma unroll
        for (int k = 0; k < BK; k++) {
            float a[TM], b[TN];
#pragma unroll
            for (int i = 0; i < TM; i++) a[i] = As[k][ty * TM + i];
#pragma unroll
            for (int j = 0; j < TN; j++) b[j] = Bs[k][tx * TN + j];
#pragma unroll
            for (int i = 0; i < TM; i++)
#pragma unroll
                for (int j = 0; j < TN; j++) acc[i][j] += a[i] * b[j];
        }
        __syncthreads();
    }
#pragma unroll
    for (int i = 0; i < TM; i++) {
        int r = row0 + ty * TM + i;
#pragma unroll
        for (int j = 0; j < TN; j++) {
            int c = col0 + tx * TN + j;
            if (c < N) {
                float v = acc[i][j];
                if (bias) v += bias[c];
                if (relu) v = fmaxf(v, 0.f);
                Cout[(size_t)r * N + c] = v;
            }
        }
    }
}

// ---------------- attention: one block per (b,h), one thread per query row ----
__global__ void attn_kernel(const float* __restrict__ q,
                            const float* __restrict__ k,
                            const float* __restrict__ v,
                            float* __restrict__ out) {
    extern __shared__ float sh[];          // ks[T][HS] ++ vs[T][HS]  = 64 KB
    float* ks = sh;
    float* vs = sh + T_ * HS_;
    const int bh = blockIdx.x;
    const int b = bh / H_;
    const int h = bh % H_;
    const int t = threadIdx.x;             // query index 0..T-1

    // stage K,V for this (b,h)
    for (int i = threadIdx.x; i < T_ * HS_; i += blockDim.x) {
        int j = i / HS_, d = i % HS_;
        size_t src = (size_t)(b * T_ + j) * C_ + h * HS_ + d;
        ks[j * HS_ + d] = k[src];
        vs[j * HS_ + d] = v[src];
    }
    __syncthreads();

    float qr[HS_];
#pragma unroll
    for (int d = 0; d < HS_; d++)
        qr[d] = q[(size_t)(b * T_ + t) * C_ + h * HS_ + d];

    const float scale = 0.0625f;           // C^-0.5 = 1/16
    float m = -INFINITY, l = 0.f;
    float acc[HS_];
#pragma unroll
    for (int d = 0; d < HS_; d++) acc[d] = 0.f;

    for (int j = 0; j <= t; j++) {
        float s = 0.f;
        const float* kj = ks + j * HS_;
#pragma unroll
        for (int d = 0; d < HS_; d++) s += qr[d] * kj[d];
        s *= scale;
        float mn = fmaxf(m, s);
        float corr = __expf(m - mn);       // 0 when m = -inf
        float p = __expf(s - mn);
        l = l * corr + p;
        const float* vj = vs + j * HS_;
#pragma unroll
        for (int d = 0; d < HS_; d++) acc[d] = acc[d] * corr + p * vj[d];
        m = mn;
    }
    float inv = 1.f / l;
#pragma unroll
    for (int d = 0; d < HS_; d++)
        out[(size_t)(b * T_ + t) * C_ + h * HS_ + d] = acc[d] * inv;
}

// ---------------- fused residual + layernorm (block per token, in-place ok) --
__global__ void add_ln_kernel(const float* __restrict__ x,
                              const float* __restrict__ add,
                              const float* __restrict__ w,
                              const float* __restrict__ b,
                              float* __restrict__ out) {
    const int row = blockIdx.x;
    const int c = threadIdx.x;             // 0..C-1 (C == 256 threads)
    float v = x[(size_t)row * C_ + c];
    if (add) v += add[(size_t)row * C_ + c];

    float s = v, s2 = v * v;
    __shared__ float sh1[8], sh2[8];
#pragma unroll
    for (int o = 16; o; o >>= 1) {
        s  += __shfl_xor_sync(0xffffffffu, s, o);
        s2 += __shfl_xor_sync(0xffffffffu, s2, o);
    }
    if ((c & 31) == 0) { sh1[c >> 5] = s; sh2[c >> 5] = s2; }
    __syncthreads();
    if (c < 32) {
        s  = (c < 8) ? sh1[c] : 0.f;
        s2 = (c < 8) ? sh2[c] : 0.f;
#pragma unroll
        for (int o = 4; o; o >>= 1) {
            s  += __shfl_xor_sync(0xffffffffu, s, o);
            s2 += __shfl_xor_sync(0xffffffffu, s2, o);
        }
        if (c == 0) { sh1[0] = s; sh2[0] = s2; }
    }
    __syncthreads();
    float mean = sh1[0] * (1.f / C_);
    float var  = sh2[0] * (1.f / C_) - mean * mean;
    out[(size_t)row * C_ + c] = (v - mean) * rsqrtf(var + EPS_) * w[c] + b[c];
}

// ---------------- per-row NLL (one warp per row over V=96 logits) -----------
__global__ void nll_kernel(const float* __restrict__ logits,
                           const int* __restrict__ tgt,
                           float* __restrict__ nll) {
    int warp = (blockIdx.x * blockDim.x + threadIdx.x) >> 5;
    int lane = threadIdx.x & 31;
    if (warp >= BT_) return;
    const float* l = logits + (size_t)warp * V_;
    float mx = -INFINITY;
    for (int c = lane; c < V_; c += 32) mx = fmaxf(mx, l[c]);
#pragma unroll
    for (int o = 16; o; o >>= 1) mx = fmaxf(mx, __shfl_xor_sync(0xffffffffu, mx, o));
    float s = 0.f;
    for (int c = lane; c < V_; c += 32) s += __expf(l[c] - mx);
#pragma unroll
    for (int o = 16; o; o >>= 1) s += __shfl_xor_sync(0xffffffffu, s, o);
    if (lane == 0) {
        int t = tgt[warp];
        nll[warp] = -(l[t] - mx - __logf(s));
    }
}

// deterministic single-block mean reduction
__global__ void reduce_loss_kernel(const float* __restrict__ nll, float* __restrict__ out) {
    __shared__ float sh[256];
    float s = 0.f;
    for (int i = threadIdx.x; i < BT_; i += 256) s += nll[i];
    sh[threadIdx.x] = s;
    __syncthreads();
    for (int st = 128; st; st >>= 1) {
        if (threadIdx.x < st) sh[threadIdx.x] += sh[threadIdx.x + st];
        __syncthreads();
    }
    if (threadIdx.x == 0) *out = sh[0] * (1.f / BT_);
}

// ---------------- host driver ----------------
extern "C" void kernel_launch(void* const* d_in, const int* in_sizes, int n_in,
                              void* d_out, int out_size) {
    const int*   idx     = (const int*)  d_in[0];
    const int*   target  = (const int*)  d_in[1];
    const float* tok_emb = (const float*)d_in[2];
    const float* pos_emb = (const float*)d_in[3];
    const float* Wq      = (const float*)d_in[4];
    const float* Wk      = (const float*)d_in[5];
    const float* Wv      = (const float*)d_in[6];
    const float* Wo      = (const float*)d_in[7];
    const float* bo      = (const float*)d_in[8];
    const float* W1      = (const float*)d_in[9];
    const float* b1      = (const float*)d_in[10];
    const float* b2_     = (const float*)d_in[12];
    const float* W2      = (const float*)d_in[11];
    const float* ln1_w   = (const float*)d_in[13];
    const float* ln1_b   = (const float*)d_in[14];
    const float* ln2_w   = (const float*)d_in[15];
    const float* ln2_b   = (const float*)d_in[16];
    const float* lnf_w   = (const float*)d_in[17];
    const float* lnf_b   = (const float*)d_in[18];
    const float* Wlm     = (const float*)d_in[19];
    const float* blm     = (const float*)d_in[20];

    float *px, *pq, *pk, *pv, *patt, *ptmp, *ph, *pnll;
    cudaGetSymbolAddress((void**)&px,   g_x);
    cudaGetSymbolAddress((void**)&pq,   g_q);
    cudaGetSymbolAddress((void**)&pk,   g_k);
    cudaGetSymbolAddress((void**)&pv,   g_v);
    cudaGetSymbolAddress((void**)&patt, g_att);
    cudaGetSymbolAddress((void**)&ptmp, g_tmp);
    cudaGetSymbolAddress((void**)&ph,   g_h);
    cudaGetSymbolAddress((void**)&pnll, g_nll);

    const int attn_smem = 2 * T_ * HS_ * sizeof(float);   // 64 KB
    cudaFuncSetAttribute(attn_kernel, cudaFuncAttributeMaxDynamicSharedMemorySize, attn_smem);

    dim3 ggrid_c((C_ + BN - 1) / BN, BT_ / BM);   // [16384 x 256] GEMMs
    dim3 ggrid_v((V_ + BN - 1) / BN, BT_ / BM);   // LM head

    embed_kernel<<<BT_, C_>>>(idx, tok_emb, pos_emb, px);

    const size_t CC = (size_t)C_ * C_;
    for (int l = 0; l < L_; l++) {
        gemm_kernel<<<ggrid_c, 256>>>(px, Wq + l * CC, nullptr, pq, BT_, C_, C_, 0);
        gemm_kernel<<<ggrid_c, 256>>>(px, Wk + l * CC, nullptr, pk, BT_, C_, C_, 0);
        gemm_kernel<<<ggrid_c, 256>>>(px, Wv + l * CC, nullptr, pv, BT_, C_, C_, 0);
        attn_kernel<<<B_ * H_, T_, attn_smem>>>(pq, pk, pv, patt);
        gemm_kernel<<<ggrid_c, 256>>>(patt, Wo + l * CC, bo + l * C_, ptmp, BT_, C_, C_, 0);
        add_ln_kernel<<<BT_, C_>>>(px, ptmp, ln1_w + l * C_, ln1_b + l * C_, px);
        gemm_kernel<<<ggrid_c, 256>>>(px, W1 + l * CC, b1 + l * C_, ph, BT_, C_, C_, 1);
        gemm_kernel<<<ggrid_c, 256>>>(ph, W2 + l * CC, b2_ + l * C_, ptmp, BT_, C_, C_, 0);
        add_ln_kernel<<<BT_, C_>>>(px, ptmp, ln2_w + l * C_, ln2_b + l * C_, px);
    }
    add_ln_kernel<<<BT_, C_>>>(px, nullptr, lnf_w, lnf_b, px);

    float* logits = (out_size >= BT_ * V_) ? (float*)d_out : ptmp;
    gemm_kernel<<<ggrid_v, 256>>>(px, Wlm, blm, logits, BT_, V_, C_, 0);

    nll_kernel<<<(BT_ * 32 + 255) / 256, 256>>>(logits, target, pnll);

    float* loss_dst = nullptr;
    if (out_size == 1)              loss_dst = (float*)d_out;
    else if (out_size > BT_ * V_)   loss_dst = (float*)d_out + BT_ * V_;
    if (loss_dst) reduce_loss_kernel<<<1, 256>>>(pnll, loss_dst);
}

// round 3
// speedup vs baseline: 2.4423x; 2.4423x over previous
#include <cuda_runtime.h>
#include <cuda_bf16.h>
#include <cstdint>
#include <math.h>

#define B_  64
#define T_  256
#define C_  256
#define H_  8
#define HS_ 32
#define L_  6
#define V_  96
#define BT_ (B_ * T_)
#define EPS_ 1e-5f

// ---------------- scratch (device globals: allocation-free) ----------------
__device__ __align__(16) float g_x  [BT_ * C_];
__device__ __align__(16) float g_q  [BT_ * C_];
__device__ __align__(16) float g_k  [BT_ * C_];
__device__ __align__(16) float g_v  [BT_ * C_];
__device__ __align__(16) float g_tmp[BT_ * C_];
__device__ __align__(16) float g_nll[BT_];

// bf16 hi/lo activation buffers
__device__ __align__(16) __nv_bfloat16 g_xh [BT_ * C_];
__device__ __align__(16) __nv_bfloat16 g_xl [BT_ * C_];
__device__ __align__(16) __nv_bfloat16 g_ah [BT_ * C_];
__device__ __align__(16) __nv_bfloat16 g_al [BT_ * C_];
__device__ __align__(16) __nv_bfloat16 g_hh [BT_ * C_];
__device__ __align__(16) __nv_bfloat16 g_hl [BT_ * C_];

// transposed bf16 hi/lo weights: [Wq(6) Wk(6) Wv(6) Wo(6) W1(6) W2(6) WlmPad]
#define WMAT_ELEMS (C_ * C_)
#define WLM_ROWS   128                 // V=96 zero-padded to 128
#define W_TOTAL    (36 * WMAT_ELEMS + WLM_ROWS * C_)
__device__ __align__(16) __nv_bfloat16 g_wh[W_TOTAL];
__device__ __align__(16) __nv_bfloat16 g_wl[W_TOTAL];
#define WOFF(t, l) ((size_t)((t) * 6 + (l)) * WMAT_ELEMS)
#define WOFF_LM    ((size_t)36 * WMAT_ELEMS)

// ---------------- helpers ----------------
__device__ __forceinline__ uint32_t smem_u32(const void* p) {
    uint32_t a;
    asm("{ .reg .u64 t; cvta.to.shared.u64 t, %1; cvt.u32.u64 %0, t; }"
        : "=r"(a) : "l"(p));
    return a;
}
__device__ __forceinline__ void cp_async16(uint32_t dst, const void* src) {
    asm volatile("cp.async.cg.shared.global [%0], [%1], 16;"
                 :: "r"(dst), "l"(src) : "memory");
}
__device__ __forceinline__ void cp_commit() {
    asm volatile("cp.async.commit_group;" ::: "memory");
}
template <int N>
__device__ __forceinline__ void cp_wait() {
    asm volatile("cp.async.wait_group %0;" :: "n"(N) : "memory");
}
__device__ __forceinline__ void ldmatrix_x4(uint32_t* r, uint32_t addr) {
    asm volatile("ldmatrix.sync.aligned.m8n8.x4.shared.b16 {%0,%1,%2,%3}, [%4];"
                 : "=r"(r[0]), "=r"(r[1]), "=r"(r[2]), "=r"(r[3]) : "r"(addr));
}
__device__ __forceinline__ void ldmatrix_x2(uint32_t* r, uint32_t addr) {
    asm volatile("ldmatrix.sync.aligned.m8n8.x2.shared.b16 {%0,%1}, [%2];"
                 : "=r"(r[0]), "=r"(r[1]) : "r"(addr));
}
__device__ __forceinline__ void mma16816(float* c, const uint32_t* a, const uint32_t* b) {
    asm volatile(
        "mma.sync.aligned.m16n8k16.row.col.f32.bf16.bf16.f32 "
        "{%0,%1,%2,%3}, {%4,%5,%6,%7}, {%8,%9}, {%0,%1,%2,%3};"
        : "+f"(c[0]), "+f"(c[1]), "+f"(c[2]), "+f"(c[3])
        : "r"(a[0]), "r"(a[1]), "r"(a[2]), "r"(a[3]), "r"(b[0]), "r"(b[1]));
}

// ---------------- weight transpose + bf16 hi/lo convert (with zero pad) ----
// src: [K, Nsrc] fp32;  dst: [Ndst, K] bf16 hi/lo (rows >= Nsrc zero)
__global__ void convw_kernel(const float* __restrict__ src,
                             __nv_bfloat16* __restrict__ hi,
                             __nv_bfloat16* __restrict__ lo,
                             int K, int Nsrc, int Ndst) {
    const size_t mat = blockIdx.y;
    const float* s = src + mat * (size_t)K * Nsrc;
    __nv_bfloat16* ho = hi + mat * (size_t)Ndst * K;
    __nv_bfloat16* lg = lo + mat * (size_t)Ndst * K;
    int i = blockIdx.x * 256 + threadIdx.x;
    if (i < Ndst * K) {
        int n = i / K, k = i % K;
        float v = (n < Nsrc) ? s[(size_t)k * Nsrc + n] : 0.f;
        __nv_bfloat16 h = __float2bfloat16(v);
        ho[i] = h;
        lg[i] = __float2bfloat16(v - __bfloat162float(h));
    }
}

// ---------------- embedding ----------------
__global__ void embed_kernel(const int* __restrict__ idx,
                             const float* __restrict__ tok_emb,
                             const float* __restrict__ pos_emb,
                             float* __restrict__ x,
                             __nv_bfloat16* __restrict__ xh,
                             __nv_bfloat16* __restrict__ xl) {
    int bt = blockIdx.x;
    int c  = threadIdx.x;
    int t  = bt % T_;
    int tok = idx[bt];
    float v = tok_emb[tok * C_ + c] + pos_emb[t * C_ + c];
    size_t o = (size_t)bt * C_ + c;
    x[o] = v;
    __nv_bfloat16 h = __float2bfloat16(v);
    xh[o] = h;
    xl[o] = __float2bfloat16(v - __bfloat162float(h));
}

// ---------------- HMMA GEMM: out[M,Nout] = A[M,256] @ Bt[Ncta*gridy,256]^T --
// 3-term bf16 split (AhBh + AhBl + AlBh) as a K=768 loop; fp32 accum.
// CTA 128x128, 8 warps (2 M x 4 N), warp tile 64x32, cp.async double buffer.
__global__ void __launch_bounds__(256)
hmma_gemm(const __nv_bfloat16* __restrict__ Ah, const __nv_bfloat16* __restrict__ Al,
          const __nv_bfloat16* __restrict__ Bh, const __nv_bfloat16* __restrict__ Bl,
          float* __restrict__ outF,
          __nv_bfloat16* __restrict__ outH, __nv_bfloat16* __restrict__ outL,
          const float* __restrict__ bias, int relu, int Nout) {
    extern __shared__ char smem[];
    const uint32_t sb = smem_u32(smem);

    const int tid  = threadIdx.x;
    const int lane = tid & 31;
    const int w    = tid >> 5;
    const int wm   = w & 1;          // 0..1  (64 rows each)
    const int wn   = w >> 1;         // 0..3  (32 cols each)

    const size_t rowblock = (size_t)blockIdx.x * 128;
    const int    colblock = blockIdx.y * 128;

    const __nv_bfloat16* Asrc[3] = {Ah, Ah, Al};
    const __nv_bfloat16* Bsrc[3] = {Bh, Bl, Bh};

    float acc[4][4][4];
#pragma unroll
    for (int i = 0; i < 4; i++)
#pragma unroll
        for (int j = 0; j < 4; j++)
#pragma unroll
            for (int r = 0; r < 4; r++) acc[i][j][r] = 0.f;

    // stage s (0..11): pass p = s>>2, k0 = (s&3)*64; buffers of 32 KB (A 16K + B 16K)
    auto load_stage = [&](int s, int buf) {
        const int p  = s >> 2;
        const int k0 = (s & 3) * 64;
        const __nv_bfloat16* Ap = Asrc[p];
        const __nv_bfloat16* Bp = Bsrc[p];
        const uint32_t base = sb + buf * 32768;
#pragma unroll
        for (int it = 0; it < 4; it++) {
            int chunk = tid + it * 256;          // 0..1023
            int r = chunk >> 3, h = chunk & 7;   // row, 16B-half
            uint32_t off = (uint32_t)(r * 128 + 16 * (h ^ (r & 7)));
            cp_async16(base + off,          Ap + (rowblock + r) * 256 + k0 + h * 8);
            cp_async16(base + 16384 + off,  Bp + (size_t)(colblock + r) * 256 + k0 + h * 8);
        }
        cp_commit();
    };

    load_stage(0, 0);

    for (int s = 0; s < 12; s++) {
        if (s < 11) load_stage(s + 1, (s + 1) & 1);
        if (s < 11) cp_wait<1>(); else cp_wait<0>();
        __syncthreads();

        const uint32_t base = sb + (s & 1) * 32768;
#pragma unroll
        for (int ks = 0; ks < 4; ks++) {
            uint32_t a[4][4];
#pragma unroll
            for (int i = 0; i < 4; i++) {
                int r = wm * 64 + i * 16 + (lane & 15);
                int h = 2 * ks + (lane >> 4);
                ldmatrix_x4(a[i], base + r * 128 + 16 * (h ^ (r & 7)));
            }
            uint32_t b[4][2];
#pragma unroll
            for (int j = 0; j < 4; j++) {
                int r = wn * 32 + j * 8 + (lane & 7);
                int h = 2 * ks + ((lane >> 3) & 1);
                ldmatrix_x2(b[j], base + 16384 + r * 128 + 16 * (h ^ (r & 7)));
            }
#pragma unroll
            for (int i = 0; i < 4; i++)
#pragma unroll
                for (int j = 0; j < 4; j++) mma16816(acc[i][j], a[i], b[j]);
        }
        __syncthreads();
    }

    // ---- epilogue ----
    const int g  = lane >> 2;
    const int tg = lane & 3;
#pragma unroll
    for (int i = 0; i < 4; i++) {
#pragma unroll
        for (int j = 0; j < 4; j++) {
            int col = colblock + wn * 32 + j * 8 + tg * 2;
            if (col >= Nout) continue;
            size_t r0 = rowblock + wm * 64 + i * 16 + g;
            size_t r1 = r0 + 8;
            float b0 = bias ? bias[col] : 0.f;
            float b1 = bias ? bias[col + 1] : 0.f;
            float v00 = acc[i][j][0] + b0, v01 = acc[i][j][1] + b1;
            float v10 = acc[i][j][2] + b0, v11 = acc[i][j][3] + b1;
            if (relu) {
                v00 = fmaxf(v00, 0.f); v01 = fmaxf(v01, 0.f);
                v10 = fmaxf(v10, 0.f); v11 = fmaxf(v11, 0.f);
            }
            if (outF) {
                *(float2*)(outF + r0 * Nout + col) = make_float2(v00, v01);
                *(float2*)(outF + r1 * Nout + col) = make_float2(v10, v11);
            }
            if (outH) {
                __nv_bfloat16 h00 = __float2bfloat16(v00), h01 = __float2bfloat16(v01);
                __nv_bfloat16 h10 = __float2bfloat16(v10), h11 = __float2bfloat16(v11);
                *(__nv_bfloat162*)(outH + r0 * Nout + col) = __nv_bfloat162(h00, h01);
                *(__nv_bfloat162*)(outH + r1 * Nout + col) = __nv_bfloat162(h10, h11);
                *(__nv_bfloat162*)(outL + r0 * Nout + col) = __nv_bfloat162(
                    __float2bfloat16(v00 - __bfloat162float(h00)),
                    __float2bfloat16(v01 - __bfloat162float(h01)));
                *(__nv_bfloat162*)(outL + r1 * Nout + col) = __nv_bfloat162(
                    __float2bfloat16(v10 - __bfloat162float(h10)),
                    __float2bfloat16(v11 - __bfloat162float(h11)));
            }
        }
    }
}

// ---------------- attention (fp32 in, bf16 hi/lo out) ----------------
__global__ void attn_kernel(const float* __restrict__ q,
                            const float* __restrict__ k,
                            const float* __restrict__ v,
                            __nv_bfloat16* __restrict__ outH,
                            __nv_bfloat16* __restrict__ outL) {
    extern __shared__ float sh[];
    float* ks = sh;
    float* vs = sh + T_ * HS_;
    const int bh = blockIdx.x;
    const int b = bh / H_;
    const int h = bh % H_;
    const int t = threadIdx.x;

    for (int i = threadIdx.x; i < T_ * HS_; i += blockDim.x) {
        int j = i / HS_, d = i % HS_;
        size_t src = (size_t)(b * T_ + j) * C_ + h * HS_ + d;
        ks[j * HS_ + d] = k[src];
        vs[j * HS_ + d] = v[src];
    }
    __syncthreads();

    float qr[HS_];
#pragma unroll
    for (int d = 0; d < HS_; d++)
        qr[d] = q[(size_t)(b * T_ + t) * C_ + h * HS_ + d];

    const float scale = 0.0625f;
    float m = -INFINITY, l = 0.f;
    float acc[HS_];
#pragma unroll
    for (int d = 0; d < HS_; d++) acc[d] = 0.f;

    for (int j = 0; j <= t; j++) {
        float s = 0.f;
        const float* kj = ks + j * HS_;
#pragma unroll
        for (int d = 0; d < HS_; d++) s += qr[d] * kj[d];
        s *= scale;
        float mn = fmaxf(m, s);
        float corr = __expf(m - mn);
        float p = __expf(s - mn);
        l = l * corr + p;
        const float* vj = vs + j * HS_;
#pragma unroll
        for (int d = 0; d < HS_; d++) acc[d] = acc[d] * corr + p * vj[d];
        m = mn;
    }
    float inv = 1.f / l;
#pragma unroll
    for (int d = 0; d < HS_; d++) {
        float o = acc[d] * inv;
        size_t dst = (size_t)(b * T_ + t) * C_ + h * HS_ + d;
        __nv_bfloat16 hi = __float2bfloat16(o);
        outH[dst] = hi;
        outL[dst] = __float2bfloat16(o - __bfloat162float(hi));
    }
}

// ---------------- fused residual + layernorm ----------------
__global__ void add_ln_kernel(const float* __restrict__ x,
                              const float* __restrict__ add,
                              const float* __restrict__ w,
                              const float* __restrict__ b,
                              float* __restrict__ out,
                              __nv_bfloat16* __restrict__ outH,
                              __nv_bfloat16* __restrict__ outL) {
    const int row = blockIdx.x;
    const int c = threadIdx.x;
    float v = x[(size_t)row * C_ + c];
    if (add) v += add[(size_t)row * C_ + c];

    float s = v, s2 = v * v;
    __shared__ float sh1[8], sh2[8];
#pragma unroll
    for (int o = 16; o; o >>= 1) {
        s  += __shfl_xor_sync(0xffffffffu, s, o);
        s2 += __shfl_xor_sync(0xffffffffu, s2, o);
    }
    if ((c & 31) == 0) { sh1[c >> 5] = s; sh2[c >> 5] = s2; }
    __syncthreads();
    if (c < 32) {
        s  = (c < 8) ? sh1[c] : 0.f;
        s2 = (c < 8) ? sh2[c] : 0.f;
#pragma unroll
        for (int o = 4; o; o >>= 1) {
            s  += __shfl_xor_sync(0xffffffffu, s, o);
            s2 += __shfl_xor_sync(0xffffffffu, s2, o);
        }
        if (c == 0) { sh1[0] = s; sh2[0] = s2; }
    }
    __syncthreads();
    float mean = sh1[0] * (1.f / C_);
    float var  = sh2[0] * (1.f / C_) - mean * mean;
    float r = (v - mean) * rsqrtf(var + EPS_) * w[c] + b[c];
    size_t o = (size_t)row * C_ + c;
    if (out) out[o] = r;
    __nv_bfloat16 hi = __float2bfloat16(r);
    outH[o] = hi;
    outL[o] = __float2bfloat16(r - __bfloat162float(hi));
}

// ---------------- per-row NLL ----------------
__global__ void nll_kernel(const float* __restrict__ logits,
                           const int* __restrict__ tgt,
                           float* __restrict__ nll) {
    int warp = (blockIdx.x * blockDim.x + threadIdx.x) >> 5;
    int lane = threadIdx.x & 31;
    if (warp >= BT_) return;
    const float* l = logits + (size_t)warp * V_;
    float mx = -INFINITY;
    for (int c = lane; c < V_; c += 32) mx = fmaxf(mx, l[c]);
#pragma unroll
    for (int o = 16; o; o >>= 1) mx = fmaxf(mx, __shfl_xor_sync(0xffffffffu, mx, o));
    float s = 0.f;
    for (int c = lane; c < V_; c += 32) s += __expf(l[c] - mx);
#pragma unroll
    for (int o = 16; o; o >>= 1) s += __shfl_xor_sync(0xffffffffu, s, o);
    if (lane == 0) {
        int t = tgt[warp];
        nll[warp] = -(l[t] - mx - __logf(s));
    }
}

__global__ void reduce_loss_kernel(const float* __restrict__ nll, float* __restrict__ out) {
    __shared__ float sh[256];
    float s = 0.f;
    for (int i = threadIdx.x; i < BT_; i += 256) s += nll[i];
    sh[threadIdx.x] = s;
    __syncthreads();
    for (int st = 128; st; st >>= 1) {
        if (threadIdx.x < st) sh[threadIdx.x] += sh[threadIdx.x + st];
        __syncthreads();
    }
    if (threadIdx.x == 0) *out = sh[0] * (1.f / BT_);
}

// ---------------- host driver ----------------
extern "C" void kernel_launch(void* const* d_in, const int* in_sizes, int n_in,
                              void* d_out, int out_size) {
    const int*   idx     = (const int*)  d_in[0];
    const int*   target  = (const int*)  d_in[1];
    const float* tok_emb = (const float*)d_in[2];
    const float* pos_emb = (const float*)d_in[3];
    const float* Wq      = (const float*)d_in[4];
    const float* Wk      = (const float*)d_in[5];
    const float* Wv      = (const float*)d_in[6];
    const float* Wo      = (const float*)d_in[7];
    const float* bo      = (const float*)d_in[8];
    const float* W1      = (const float*)d_in[9];
    const float* b1      = (const float*)d_in[10];
    const float* W2      = (const float*)d_in[11];
    const float* b2_     = (const float*)d_in[12];
    const float* ln1_w   = (const float*)d_in[13];
    const float* ln1_b   = (const float*)d_in[14];
    const float* ln2_w   = (const float*)d_in[15];
    const float* ln2_b   = (const float*)d_in[16];
    const float* lnf_w   = (const float*)d_in[17];
    const float* lnf_b   = (const float*)d_in[18];
    const float* Wlm     = (const float*)d_in[19];
    const float* blm     = (const float*)d_in[20];

    float *px, *pq, *pk, *pv, *ptmp, *pnll;
    __nv_bfloat16 *pxh, *pxl, *pah, *pal, *phh, *phl, *pwh, *pwl;
    cudaGetSymbolAddress((void**)&px,   g_x);
    cudaGetSymbolAddress((void**)&pq,   g_q);
    cudaGetSymbolAddress((void**)&pk,   g_k);
    cudaGetSymbolAddress((void**)&pv,   g_v);
    cudaGetSymbolAddress((void**)&ptmp, g_tmp);
    cudaGetSymbolAddress((void**)&pnll, g_nll);
    cudaGetSymbolAddress((void**)&pxh,  g_xh);
    cudaGetSymbolAddress((void**)&pxl,  g_xl);
    cudaGetSymbolAddress((void**)&pah,  g_ah);
    cudaGetSymbolAddress((void**)&pal,  g_al);
    cudaGetSymbolAddress((void**)&phh,  g_hh);
    cudaGetSymbolAddress((void**)&phl,  g_hl);
    cudaGetSymbolAddress((void**)&pwh,  g_wh);
    cudaGetSymbolAddress((void**)&pwl,  g_wl);

    const int attn_smem = 2 * T_ * HS_ * sizeof(float);   // 64 KB
    cudaFuncSetAttribute(attn_kernel, cudaFuncAttributeMaxDynamicSharedMemorySize, attn_smem);
    const int gemm_smem = 65536;                          // 2 x (16K A + 16K B)
    cudaFuncSetAttribute(hmma_gemm, cudaFuncAttributeMaxDynamicSharedMemorySize, gemm_smem);

    // ---- weight transpose + hi/lo conversion ----
    {
        dim3 gw((WMAT_ELEMS + 255) / 256, 6);
        convw_kernel<<<gw, 256>>>(Wq, pwh + WOFF(0, 0), pwl + WOFF(0, 0), C_, C_, C_);
        convw_kernel<<<gw, 256>>>(Wk, pwh + WOFF(1, 0), pwl + WOFF(1, 0), C_, C_, C_);
        convw_kernel<<<gw, 256>>>(Wv, pwh + WOFF(2, 0), pwl + WOFF(2, 0), C_, C_, C_);
        convw_kernel<<<gw, 256>>>(Wo, pwh + WOFF(3, 0), pwl + WOFF(3, 0), C_, C_, C_);
        convw_kernel<<<gw, 256>>>(W1, pwh + WOFF(4, 0), pwl + WOFF(4, 0), C_, C_, C_);
        convw_kernel<<<gw, 256>>>(W2, pwh + WOFF(5, 0), pwl + WOFF(5, 0), C_, C_, C_);
        dim3 gl((WLM_ROWS * C_ + 255) / 256, 1);
        convw_kernel<<<gl, 256>>>(Wlm, pwh + WOFF_LM, pwl + WOFF_LM, C_, V_, WLM_ROWS);
    }

    embed_kernel<<<BT_, C_>>>(idx, tok_emb, pos_emb, px, pxh, pxl);

    const dim3 grid256(BT_ / 128, 2);
    const dim3 gridLM (BT_ / 128, 1);
    for (int l = 0; l < L_; l++) {
        hmma_gemm<<<grid256, 256, gemm_smem>>>(pxh, pxl,
            pwh + WOFF(0, l), pwl + WOFF(0, l), pq, nullptr, nullptr, nullptr, 0, C_);
        hmma_gemm<<<grid256, 256, gemm_smem>>>(pxh, pxl,
            pwh + WOFF(1, l), pwl + WOFF(1, l), pk, nullptr, nullptr, nullptr, 0, C_);
        hmma_gemm<<<grid256, 256, gemm_smem>>>(pxh, pxl,
            pwh + WOFF(2, l), pwl + WOFF(2, l), pv, nullptr, nullptr, nullptr, 0, C_);
        attn_kernel<<<B_ * H_, T_, attn_smem>>>(pq, pk, pv, pah, pal);
        hmma_gemm<<<grid256, 256, gemm_smem>>>(pah, pal,
            pwh + WOFF(3, l), pwl + WOFF(3, l), ptmp, nullptr, nullptr, bo + l * C_, 0, C_);
        add_ln_kernel<<<BT_, C_>>>(px, ptmp, ln1_w + l * C_, ln1_b + l * C_, px, pxh, pxl);
        hmma_gemm<<<grid256, 256, gemm_smem>>>(pxh, pxl,
            pwh + WOFF(4, l), pwl + WOFF(4, l), nullptr, phh, phl, b1 + l * C_, 1, C_);
        hmma_gemm<<<grid256, 256, gemm_smem>>>(phh, phl,
            pwh + WOFF(5, l), pwl + WOFF(5, l), ptmp, nullptr, nullptr, b2_ + l * C_, 0, C_);
        add_ln_kernel<<<BT_, C_>>>(px, ptmp, ln2_w + l * C_, ln2_b + l * C_, px, pxh, pxl);
    }
    add_ln_kernel<<<BT_, C_>>>(px, nullptr, lnf_w, lnf_b, nullptr, pxh, pxl);

    float* logits = (out_size >= BT_ * V_) ? (float*)d_out : ptmp;
    hmma_gemm<<<gridLM, 256, gemm_smem>>>(pxh, pxl,
        pwh + WOFF_LM, pwl + WOFF_LM, logits, nullptr, nullptr, blm, 0, V_);

    nll_kernel<<<(BT_ * 32 + 255) / 256, 256>>>(logits, target, pnll);

    float* loss_dst = nullptr;
    if (out_size == 1)              loss_dst = (float*)d_out;
    else if (out_size > BT_ * V_)   loss_dst = (float*)d_out + BT_ * V_;
    if (loss_dst) reduce_loss_kernel<<<1, 256>>>(pnll, loss_dst);
}

// round 4
// speedup vs baseline: 2.5669x; 1.0510x over previous
#include <cuda_runtime.h>
#include <cuda_bf16.h>
#include <cstdint>
#include <math.h>

#define B_  64
#define T_  256
#define C_  256
#define H_  8
#define HS_ 32
#define L_  6
#define V_  96
#define BT_ (B_ * T_)
#define EPS_ 1e-5f

// ---------------- scratch (device globals) ----------------
__device__ __align__(16) float g_x  [BT_ * C_];
__device__ __align__(16) float g_qkv[3 * BT_ * C_];
__device__ __align__(16) float g_nll[BT_];

__device__ __align__(16) __nv_bfloat16 g_xh [BT_ * C_];
__device__ __align__(16) __nv_bfloat16 g_xl [BT_ * C_];
__device__ __align__(16) __nv_bfloat16 g_ah [BT_ * C_];
__device__ __align__(16) __nv_bfloat16 g_al [BT_ * C_];
__device__ __align__(16) __nv_bfloat16 g_hh [BT_ * C_];
__device__ __align__(16) __nv_bfloat16 g_hl [BT_ * C_];

#define WMAT_ELEMS (C_ * C_)
#define WLM_ROWS   128
#define W_TOTAL    (36 * WMAT_ELEMS + WLM_ROWS * C_)
__device__ __align__(16) __nv_bfloat16 g_wh[W_TOTAL];
__device__ __align__(16) __nv_bfloat16 g_wl[W_TOTAL];
#define WOFF(t, l) ((size_t)((t) * 6 + (l)) * WMAT_ELEMS)
#define WOFF_LM    ((size_t)36 * WMAT_ELEMS)

// ---------------- helpers ----------------
__device__ __forceinline__ uint32_t smem_u32(const void* p) {
    uint32_t a;
    asm("{ .reg .u64 t; cvta.to.shared.u64 t, %1; cvt.u32.u64 %0, t; }"
        : "=r"(a) : "l"(p));
    return a;
}
__device__ __forceinline__ void cp_async16(uint32_t dst, const void* src) {
    asm volatile("cp.async.cg.shared.global [%0], [%1], 16;"
                 :: "r"(dst), "l"(src) : "memory");
}
__device__ __forceinline__ void cp_commit() {
    asm volatile("cp.async.commit_group;" ::: "memory");
}
template <int N>
__device__ __forceinline__ void cp_wait() {
    asm volatile("cp.async.wait_group %0;" :: "n"(N) : "memory");
}
__device__ __forceinline__ void ldmatrix_x4(uint32_t* r, uint32_t addr) {
    asm volatile("ldmatrix.sync.aligned.m8n8.x4.shared.b16 {%0,%1,%2,%3}, [%4];"
                 : "=r"(r[0]), "=r"(r[1]), "=r"(r[2]), "=r"(r[3]) : "r"(addr));
}
__device__ __forceinline__ void mma16816(float* c, const uint32_t* a, const uint32_t* b) {
    asm volatile(
        "mma.sync.aligned.m16n8k16.row.col.f32.bf16.bf16.f32 "
        "{%0,%1,%2,%3}, {%4,%5,%6,%7}, {%8,%9}, {%0,%1,%2,%3};"
        : "+f"(c[0]), "+f"(c[1]), "+f"(c[2]), "+f"(c[3])
        : "r"(a[0]), "r"(a[1]), "r"(a[2]), "r"(a[3]), "r"(b[0]), "r"(b[1]));
}

// ---------------- merged weight transpose + hi/lo (ALL 37 matrices) --------
__global__ void convw_all(const float* __restrict__ Wq, const float* __restrict__ Wk,
                          const float* __restrict__ Wv, const float* __restrict__ Wo,
                          const float* __restrict__ W1, const float* __restrict__ W2,
                          const float* __restrict__ Wlm,
                          __nv_bfloat16* __restrict__ hi, __nv_bfloat16* __restrict__ lo) {
    const int mat = blockIdx.y;
    const int i = blockIdx.x * 256 + threadIdx.x;
    float v;
    size_t o;
    if (mat < 36) {
        if (i >= WMAT_ELEMS) return;
        const float* srcs[6] = {Wq, Wk, Wv, Wo, W1, W2};
        int t = mat / 6, l = mat % 6;
        const float* s = srcs[t] + (size_t)l * WMAT_ELEMS;
        int n = i >> 8, k = i & 255;
        v = s[(size_t)k * 256 + n];
        o = (size_t)mat * WMAT_ELEMS + i;
    } else {
        if (i >= WLM_ROWS * C_) return;
        int n = i >> 8, k = i & 255;
        v = (n < V_) ? Wlm[(size_t)k * V_ + n] : 0.f;
        o = WOFF_LM + i;
    }
    __nv_bfloat16 h = __float2bfloat16(v);
    hi[o] = h;
    lo[o] = __float2bfloat16(v - __bfloat162float(h));
}

// ---------------- embedding ----------------
__global__ void embed_kernel(const int* __restrict__ idx,
                             const float* __restrict__ tok_emb,
                             const float* __restrict__ pos_emb,
                             float* __restrict__ x,
                             __nv_bfloat16* __restrict__ xh,
                             __nv_bfloat16* __restrict__ xl) {
    int bt = blockIdx.x;
    int c  = threadIdx.x;
    int t  = bt % T_;
    int tok = idx[bt];
    float v = tok_emb[tok * C_ + c] + pos_emb[t * C_ + c];
    size_t o = (size_t)bt * C_ + c;
    x[o] = v;
    __nv_bfloat16 h = __float2bfloat16(v);
    xh[o] = h;
    xl[o] = __float2bfloat16(v - __bfloat162float(h));
}

// ---------------- HMMA GEMM, CTA tile 128 x NT, fused epilogues ------------
// MODE 0: fp32 out (+bias), Nout cols.  MODE 1: relu, bf16 hi/lo out.
// MODE 2: +bias +residual -> LayerNorm -> fp32 x + bf16 hi/lo out.
// 3-term bf16 split (AhBh + AhBl + AlBh), K=256 per pass, 12 stages of 64.
template <int NT, int FJ, int MODE>
__global__ void __launch_bounds__(512)
hmma_gemm2(const __nv_bfloat16* __restrict__ Ah, const __nv_bfloat16* __restrict__ Al,
           const __nv_bfloat16* __restrict__ BhBase, const __nv_bfloat16* __restrict__ BlBase,
           size_t wstride, float* outF, size_t ostride,
           __nv_bfloat16* __restrict__ outH, __nv_bfloat16* __restrict__ outL,
           const float* __restrict__ bias, const float* __restrict__ res,
           const float* __restrict__ lnw, const float* __restrict__ lnb, int Nout) {
    extern __shared__ char smem[];
    const uint32_t sb = smem_u32(smem);
    constexpr int STAGE = 16384 + NT * 128;      // A 16KB + B NT*128B
    constexpr int NCHUNK = 1024 + NT * 8;        // 16B chunks per stage
    constexpr int WN = NT / 4;                   // warp n-tile

    const int tid  = threadIdx.x;
    const int lane = tid & 31;
    const int w    = tid >> 5;
    const int wm   = w & 3;       // 4 M groups of 32 rows
    const int wn   = w >> 2;      // 4 N groups of WN cols

    const size_t rowblock = (size_t)blockIdx.x * 128;
    const __nv_bfloat16* Bh = BhBase + blockIdx.y * wstride;
    const __nv_bfloat16* Bl = BlBase + blockIdx.y * wstride;
    if (MODE == 0) outF += blockIdx.y * ostride;

    const __nv_bfloat16* Asrc[3] = {Ah, Ah, Al};
    const __nv_bfloat16* Bsrc[3] = {Bh, Bl, Bh};

    float acc[2][FJ][4];
#pragma unroll
    for (int i = 0; i < 2; i++)
#pragma unroll
        for (int j = 0; j < FJ; j++)
#pragma unroll
            for (int r = 0; r < 4; r++) acc[i][j][r] = 0.f;

    auto load_stage = [&](int s, int buf) {
        const int p  = s >> 2;
        const int k0 = (s & 3) * 64;
        const __nv_bfloat16* Ap = Asrc[p];
        const __nv_bfloat16* Bp = Bsrc[p];
        const uint32_t base = sb + buf * STAGE;
#pragma unroll
        for (int c = tid; c < NCHUNK; c += 512) {
            if (c < 1024) {
                int r = c >> 3, h = c & 7;
                cp_async16(base + r * 128 + 16 * (h ^ (r & 7)),
                           Ap + (rowblock + r) * 256 + k0 + h * 8);
            } else {
                int cc = c - 1024;
                int r = cc >> 3, h = cc & 7;
                cp_async16(base + 16384 + r * 128 + 16 * (h ^ (r & 7)),
                           Bp + (size_t)r * 256 + k0 + h * 8);
            }
        }
        cp_commit();
    };

    load_stage(0, 0);

    for (int s = 0; s < 12; s++) {
        if (s < 11) { load_stage(s + 1, (s + 1) & 1); cp_wait<1>(); }
        else        { cp_wait<0>(); }
        __syncthreads();

        const uint32_t base = sb + (s & 1) * STAGE;
#pragma unroll
        for (int ks = 0; ks < 4; ks++) {
            uint32_t a[2][4];
#pragma unroll
            for (int i = 0; i < 2; i++) {
                int r = wm * 32 + i * 16 + (lane & 15);
                int h = 2 * ks + (lane >> 4);
                ldmatrix_x4(a[i], base + r * 128 + 16 * (h ^ (r & 7)));
            }
            uint32_t b[FJ][2];
#pragma unroll
            for (int j2 = 0; j2 < FJ / 2; j2++) {
                int r = wn * WN + j2 * 16 + ((lane >> 4) & 1) * 8 + (lane & 7);
                int h = 2 * ks + ((lane >> 3) & 1);
                uint32_t t4[4];
                ldmatrix_x4(t4, base + 16384 + r * 128 + 16 * (h ^ (r & 7)));
                b[2 * j2][0]     = t4[0];
                b[2 * j2][1]     = t4[1];
                b[2 * j2 + 1][0] = t4[2];
                b[2 * j2 + 1][1] = t4[3];
            }
#pragma unroll
            for (int i = 0; i < 2; i++)
#pragma unroll
                for (int j = 0; j < FJ; j++) mma16816(acc[i][j], a[i], b[j]);
        }
        __syncthreads();
    }

    // ---- epilogue ----
    const int g  = lane >> 2;
    const int tg = lane & 3;

    if (MODE == 0) {
#pragma unroll
        for (int i = 0; i < 2; i++) {
#pragma unroll
            for (int j = 0; j < FJ; j++) {
                int col = wn * WN + j * 8 + tg * 2;
                if (col + 1 >= Nout) continue;
                size_t r0 = rowblock + wm * 32 + i * 16 + g;
                size_t r1 = r0 + 8;
                float b0 = bias ? bias[col] : 0.f;
                float b1 = bias ? bias[col + 1] : 0.f;
                *(float2*)(outF + r0 * Nout + col) =
                    make_float2(acc[i][j][0] + b0, acc[i][j][1] + b1);
                *(float2*)(outF + r1 * Nout + col) =
                    make_float2(acc[i][j][2] + b0, acc[i][j][3] + b1);
            }
        }
    } else if (MODE == 1) {
#pragma unroll
        for (int i = 0; i < 2; i++) {
#pragma unroll
            for (int j = 0; j < FJ; j++) {
                int col = wn * WN + j * 8 + tg * 2;
                size_t r0 = rowblock + wm * 32 + i * 16 + g;
                size_t r1 = r0 + 8;
                float b0 = bias[col], b1 = bias[col + 1];
                float v00 = fmaxf(acc[i][j][0] + b0, 0.f);
                float v01 = fmaxf(acc[i][j][1] + b1, 0.f);
                float v10 = fmaxf(acc[i][j][2] + b0, 0.f);
                float v11 = fmaxf(acc[i][j][3] + b1, 0.f);
                __nv_bfloat16 h00 = __float2bfloat16(v00), h01 = __float2bfloat16(v01);
                __nv_bfloat16 h10 = __float2bfloat16(v10), h11 = __float2bfloat16(v11);
                *(__nv_bfloat162*)(outH + r0 * NT + col) = __nv_bfloat162(h00, h01);
                *(__nv_bfloat162*)(outH + r1 * NT + col) = __nv_bfloat162(h10, h11);
                *(__nv_bfloat162*)(outL + r0 * NT + col) = __nv_bfloat162(
                    __float2bfloat16(v00 - __bfloat162float(h00)),
                    __float2bfloat16(v01 - __bfloat162float(h01)));
                *(__nv_bfloat162*)(outL + r1 * NT + col) = __nv_bfloat162(
                    __float2bfloat16(v10 - __bfloat162float(h10)),
                    __float2bfloat16(v11 - __bfloat162float(h11)));
            }
        }
    } else {
        // MODE 2: v = acc + bias + residual; per-row LN over NT cols; write x + hi/lo
        float* rs = (float*)smem;            // [128][4]
        float* rq = rs + 512;                // [128][4]
        float vsum[2][2] = {{0.f, 0.f}, {0.f, 0.f}};
        float vsq [2][2] = {{0.f, 0.f}, {0.f, 0.f}};
#pragma unroll
        for (int i = 0; i < 2; i++) {
#pragma unroll
            for (int j = 0; j < FJ; j++) {
                int col = wn * WN + j * 8 + tg * 2;
                size_t r0 = rowblock + wm * 32 + i * 16 + g;
                size_t r1 = r0 + 8;
                float b0 = bias[col], b1 = bias[col + 1];
                float2 q0 = *(const float2*)(res + r0 * NT + col);
                float2 q1 = *(const float2*)(res + r1 * NT + col);
                float v00 = acc[i][j][0] + b0 + q0.x;
                float v01 = acc[i][j][1] + b1 + q0.y;
                float v10 = acc[i][j][2] + b0 + q1.x;
                float v11 = acc[i][j][3] + b1 + q1.y;
                acc[i][j][0] = v00; acc[i][j][1] = v01;
                acc[i][j][2] = v10; acc[i][j][3] = v11;
                vsum[i][0] += v00 + v01;  vsq[i][0] += v00 * v00 + v01 * v01;
                vsum[i][1] += v10 + v11;  vsq[i][1] += v10 * v10 + v11 * v11;
            }
        }
#pragma unroll
        for (int i = 0; i < 2; i++)
#pragma unroll
            for (int hf = 0; hf < 2; hf++) {
                float s = vsum[i][hf], q = vsq[i][hf];
                s += __shfl_xor_sync(0xffffffffu, s, 1);
                s += __shfl_xor_sync(0xffffffffu, s, 2);
                q += __shfl_xor_sync(0xffffffffu, q, 1);
                q += __shfl_xor_sync(0xffffffffu, q, 2);
                if (tg == 0) {
                    int lr = wm * 32 + i * 16 + hf * 8 + g;
                    rs[lr * 4 + wn] = s;
                    rq[lr * 4 + wn] = q;
                }
            }
        __syncthreads();
        float mean[2][2], rstd[2][2];
#pragma unroll
        for (int i = 0; i < 2; i++)
#pragma unroll
            for (int hf = 0; hf < 2; hf++) {
                int lr = wm * 32 + i * 16 + hf * 8 + g;
                float S = rs[lr * 4] + rs[lr * 4 + 1] + rs[lr * 4 + 2] + rs[lr * 4 + 3];
                float Q = rq[lr * 4] + rq[lr * 4 + 1] + rq[lr * 4 + 2] + rq[lr * 4 + 3];
                float mn = S * (1.f / NT);
                float var = Q * (1.f / NT) - mn * mn;
                mean[i][hf] = mn;
                rstd[i][hf] = rsqrtf(var + EPS_);
            }
#pragma unroll
        for (int i = 0; i < 2; i++) {
#pragma unroll
            for (int j = 0; j < FJ; j++) {
                int col = wn * WN + j * 8 + tg * 2;
                size_t r0 = rowblock + wm * 32 + i * 16 + g;
                size_t r1 = r0 + 8;
                float w0 = lnw[col], w1 = lnw[col + 1];
                float c0 = lnb[col], c1 = lnb[col + 1];
                float v00 = (acc[i][j][0] - mean[i][0]) * rstd[i][0] * w0 + c0;
                float v01 = (acc[i][j][1] - mean[i][0]) * rstd[i][0] * w1 + c1;
                float v10 = (acc[i][j][2] - mean[i][1]) * rstd[i][1] * w0 + c0;
                float v11 = (acc[i][j][3] - mean[i][1]) * rstd[i][1] * w1 + c1;
                *(float2*)(outF + r0 * NT + col) = make_float2(v00, v01);
                *(float2*)(outF + r1 * NT + col) = make_float2(v10, v11);
                __nv_bfloat16 h00 = __float2bfloat16(v00), h01 = __float2bfloat16(v01);
                __nv_bfloat16 h10 = __float2bfloat16(v10), h11 = __float2bfloat16(v11);
                *(__nv_bfloat162*)(outH + r0 * NT + col) = __nv_bfloat162(h00, h01);
                *(__nv_bfloat162*)(outH + r1 * NT + col) = __nv_bfloat162(h10, h11);
                *(__nv_bfloat162*)(outL + r0 * NT + col) = __nv_bfloat162(
                    __float2bfloat16(v00 - __bfloat162float(h00)),
                    __float2bfloat16(v01 - __bfloat162float(h01)));
                *(__nv_bfloat162*)(outL + r1 * NT + col) = __nv_bfloat162(
                    __float2bfloat16(v10 - __bfloat162float(h10)),
                    __float2bfloat16(v11 - __bfloat162float(h11)));
            }
        }
    }
}

// ---------------- attention (fp32 in, bf16 hi/lo out) ----------------
__global__ void attn_kernel(const float* __restrict__ qkv,
                            __nv_bfloat16* __restrict__ outH,
                            __nv_bfloat16* __restrict__ outL) {
    extern __shared__ float sh[];
    float* ks = sh;
    float* vs = sh + T_ * HS_;
    const float* q = qkv;
    const float* k = qkv + (size_t)BT_ * C_;
    const float* v = qkv + 2 * (size_t)BT_ * C_;
    const int bh = blockIdx.x;
    const int b = bh / H_;
    const int h = bh % H_;
    const int t = threadIdx.x;

    for (int i = threadIdx.x; i < T_ * HS_; i += blockDim.x) {
        int j = i / HS_, d = i % HS_;
        size_t src = (size_t)(b * T_ + j) * C_ + h * HS_ + d;
        ks[j * HS_ + d] = k[src];
        vs[j * HS_ + d] = v[src];
    }
    __syncthreads();

    float qr[HS_];
#pragma unroll
    for (int d = 0; d < HS_; d++)
        qr[d] = q[(size_t)(b * T_ + t) * C_ + h * HS_ + d];

    const float scale = 0.0625f;
    float m = -INFINITY, l = 0.f;
    float acc[HS_];
#pragma unroll
    for (int d = 0; d < HS_; d++) acc[d] = 0.f;

    for (int j = 0; j <= t; j++) {
        float s = 0.f;
        const float* kj = ks + j * HS_;
#pragma unroll
        for (int d = 0; d < HS_; d++) s += qr[d] * kj[d];
        s *= scale;
        float mn = fmaxf(m, s);
        float corr = __expf(m - mn);
        float p = __expf(s - mn);
        l = l * corr + p;
        const float* vj = vs + j * HS_;
#pragma unroll
        for (int d = 0; d < HS_; d++) acc[d] = acc[d] * corr + p * vj[d];
        m = mn;
    }
    float inv = 1.f / l;
#pragma unroll
    for (int d = 0; d < HS_; d++) {
        float o = acc[d] * inv;
        size_t dst = (size_t)(b * T_ + t) * C_ + h * HS_ + d;
        __nv_bfloat16 hi = __float2bfloat16(o);
        outH[dst] = hi;
        outL[dst] = __float2bfloat16(o - __bfloat162float(hi));
    }
}

// ---------------- standalone layernorm (final lnf only) ----------------
__global__ void add_ln_kernel(const float* __restrict__ x,
                              const float* __restrict__ w,
                              const float* __restrict__ b,
                              __nv_bfloat16* __restrict__ outH,
                              __nv_bfloat16* __restrict__ outL) {
    const int row = blockIdx.x;
    const int c = threadIdx.x;
    float v = x[(size_t)row * C_ + c];

    float s = v, s2 = v * v;
    __shared__ float sh1[8], sh2[8];
#pragma unroll
    for (int o = 16; o; o >>= 1) {
        s  += __shfl_xor_sync(0xffffffffu, s, o);
        s2 += __shfl_xor_sync(0xffffffffu, s2, o);
    }
    if ((c & 31) == 0) { sh1[c >> 5] = s; sh2[c >> 5] = s2; }
    __syncthreads();
    if (c < 32) {
        s  = (c < 8) ? sh1[c] : 0.f;
        s2 = (c < 8) ? sh2[c] : 0.f;
#pragma unroll
        for (int o = 4; o; o >>= 1) {
            s  += __shfl_xor_sync(0xffffffffu, s, o);
            s2 += __shfl_xor_sync(0xffffffffu, s2, o);
        }
        if (c == 0) { sh1[0] = s; sh2[0] = s2; }
    }
    __syncthreads();
    float mean = sh1[0] * (1.f / C_);
    float var  = sh2[0] * (1.f / C_) - mean * mean;
    float r = (v - mean) * rsqrtf(var + EPS_) * w[c] + b[c];
    size_t o = (size_t)row * C_ + c;
    __nv_bfloat16 hi = __float2bfloat16(r);
    outH[o] = hi;
    outL[o] = __float2bfloat16(r - __bfloat162float(hi));
}

// ---------------- per-row NLL + loss ----------------
__global__ void nll_kernel(const float* __restrict__ logits,
                           const int* __restrict__ tgt,
                           float* __restrict__ nll) {
    int warp = (blockIdx.x * blockDim.x + threadIdx.x) >> 5;
    int lane = threadIdx.x & 31;
    if (warp >= BT_) return;
    const float* l = logits + (size_t)warp * V_;
    float mx = -INFINITY;
    for (int c = lane; c < V_; c += 32) mx = fmaxf(mx, l[c]);
#pragma unroll
    for (int o = 16; o; o >>= 1) mx = fmaxf(mx, __shfl_xor_sync(0xffffffffu, mx, o));
    float s = 0.f;
    for (int c = lane; c < V_; c += 32) s += __expf(l[c] - mx);
#pragma unroll
    for (int o = 16; o; o >>= 1) s += __shfl_xor_sync(0xffffffffu, s, o);
    if (lane == 0) {
        int t = tgt[warp];
        nll[warp] = -(l[t] - mx - __logf(s));
    }
}

__global__ void reduce_loss_kernel(const float* __restrict__ nll, float* __restrict__ out) {
    __shared__ float sh[256];
    float s = 0.f;
    for (int i = threadIdx.x; i < BT_; i += 256) s += nll[i];
    sh[threadIdx.x] = s;
    __syncthreads();
    for (int st = 128; st; st >>= 1) {
        if (threadIdx.x < st) sh[threadIdx.x] += sh[threadIdx.x + st];
        __syncthreads();
    }
    if (threadIdx.x == 0) *out = sh[0] * (1.f / BT_);
}

// ---------------- host driver ----------------
extern "C" void kernel_launch(void* const* d_in, const int* in_sizes, int n_in,
                              void* d_out, int out_size) {
    const int*   idx     = (const int*)  d_in[0];
    const int*   target  = (const int*)  d_in[1];
    const float* tok_emb = (const float*)d_in[2];
    const float* pos_emb = (const float*)d_in[3];
    const float* Wq      = (const float*)d_in[4];
    const float* Wk      = (const float*)d_in[5];
    const float* Wv      = (const float*)d_in[6];
    const float* Wo      = (const float*)d_in[7];
    const float* bo      = (const float*)d_in[8];
    const float* W1      = (const float*)d_in[9];
    const float* b1      = (const float*)d_in[10];
    const float* W2      = (const float*)d_in[11];
    const float* b2_     = (const float*)d_in[12];
    const float* ln1_w   = (const float*)d_in[13];
    const float* ln1_b   = (const float*)d_in[14];
    const float* ln2_w   = (const float*)d_in[15];
    const float* ln2_b   = (const float*)d_in[16];
    const float* lnf_w   = (const float*)d_in[17];
    const float* lnf_b   = (const float*)d_in[18];
    const float* Wlm     = (const float*)d_in[19];
    const float* blm     = (const float*)d_in[20];

    float *px, *pqkv, *pnll;
    __nv_bfloat16 *pxh, *pxl, *pah, *pal, *phh, *phl, *pwh, *pwl;
    cudaGetSymbolAddress((void**)&px,   g_x);
    cudaGetSymbolAddress((void**)&pqkv, g_qkv);
    cudaGetSymbolAddress((void**)&pnll, g_nll);
    cudaGetSymbolAddress((void**)&pxh,  g_xh);
    cudaGetSymbolAddress((void**)&pxl,  g_xl);
    cudaGetSymbolAddress((void**)&pah,  g_ah);
    cudaGetSymbolAddress((void**)&pal,  g_al);
    cudaGetSymbolAddress((void**)&phh,  g_hh);
    cudaGetSymbolAddress((void**)&phl,  g_hl);
    cudaGetSymbolAddress((void**)&pwh,  g_wh);
    cudaGetSymbolAddress((void**)&pwl,  g_wl);

    const int attn_smem = 2 * T_ * HS_ * sizeof(float);   // 64 KB
    cudaFuncSetAttribute(attn_kernel, cudaFuncAttributeMaxDynamicSharedMemorySize, attn_smem);
    const int smem256 = 2 * (16384 + 256 * 128);          // 98304
    const int smem128 = 2 * (16384 + 128 * 128);          // 65536
    cudaFuncSetAttribute(hmma_gemm2<256, 8, 0>, cudaFuncAttributeMaxDynamicSharedMemorySize, smem256);
    cudaFuncSetAttribute(hmma_gemm2<256, 8, 1>, cudaFuncAttributeMaxDynamicSharedMemorySize, smem256);
    cudaFuncSetAttribute(hmma_gemm2<256, 8, 2>, cudaFuncAttributeMaxDynamicSharedMemorySize, smem256);
    cudaFuncSetAttribute(hmma_gemm2<128, 4, 0>, cudaFuncAttributeMaxDynamicSharedMemorySize, smem128);

    // launch 0: all weight conversions
    convw_all<<<dim3(256, 37), 256>>>(Wq, Wk, Wv, Wo, W1, W2, Wlm, pwh, pwl);
    // launch 1: embedding
    embed_kernel<<<BT_, C_>>>(idx, tok_emb, pos_emb, px, pxh, pxl);

    const size_t QKV_OSTRIDE = (size_t)BT_ * C_;
    const size_t QKV_WSTRIDE = (size_t)6 * WMAT_ELEMS;

    for (int l = 0; l < L_; l++) {
        // QKV: one launch, grid.y selects matrix + output
        hmma_gemm2<256, 8, 0><<<dim3(128, 3), 512, smem256>>>(pxh, pxl,
            pwh + WOFF(0, l), pwl + WOFF(0, l), QKV_WSTRIDE,
            pqkv, QKV_OSTRIDE, nullptr, nullptr, nullptr, nullptr, nullptr, nullptr, C_);
        attn_kernel<<<B_ * H_, T_, attn_smem>>>(pqkv, pah, pal);
        // Wo + bo + residual + LN1 -> x, xh, xl
        hmma_gemm2<256, 8, 2><<<dim3(128, 1), 512, smem256>>>(pah, pal,
            pwh + WOFF(3, l), pwl + WOFF(3, l), 0,
            px, 0, pxh, pxl, bo + l * C_, px, ln1_w + l * C_, ln1_b + l * C_, C_);
        // W1 + b1 + relu -> hh, hl
        hmma_gemm2<256, 8, 1><<<dim3(128, 1), 512, smem256>>>(pxh, pxl,
            pwh + WOFF(4, l), pwl + WOFF(4, l), 0,
            nullptr, 0, phh, phl, b1 + l * C_, nullptr, nullptr, nullptr, C_);
        // W2 + b2 + residual + LN2 -> x, xh, xl
        hmma_gemm2<256, 8, 2><<<dim3(128, 1), 512, smem256>>>(phh, phl,
            pwh + WOFF(5, l), pwl + WOFF(5, l), 0,
            px, 0, pxh, pxl, b2_ + l * C_, px, ln2_w + l * C_, ln2_b + l * C_, C_);
    }
    // final LN
    add_ln_kernel<<<BT_, C_>>>(px, lnf_w, lnf_b, pxh, pxl);

    float* logits = (out_size >= BT_ * V_) ? (float*)d_out : pqkv;
    hmma_gemm2<128, 4, 0><<<dim3(128, 1), 512, smem128>>>(pxh, pxl,
        pwh + WOFF_LM, pwl + WOFF_LM, 0,
        logits, 0, nullptr, nullptr, blm, nullptr, nullptr, nullptr, V_);

    nll_kernel<<<(BT_ * 32 + 255) / 256, 256>>>(logits, target, pnll);

    float* loss_dst = nullptr;
    if (out_size == 1)              loss_dst = (float*)d_out;
    else if (out_size > BT_ * V_)   loss_dst = (float*)d_out + BT_ * V_;
    if (loss_dst) reduce_loss_kernel<<<1, 256>>>(pnll, loss_dst);
}

// round 5
// speedup vs baseline: 4.5621x; 1.7773x over previous
#include <cuda_runtime.h>
#include <cuda_bf16.h>
#include <cstdint>
#include <math.h>

#define B_  64
#define T_  256
#define C_  256
#define H_  8
#define HS_ 32
#define L_  6
#define V_  96
#define BT_ (B_ * T_)
#define EPS_ 1e-5f

// ---------------- scratch (device globals) ----------------
__device__ __align__(16) float g_x  [BT_ * C_];
__device__ __align__(16) float g_qkv[3 * BT_ * C_];
__device__ __align__(16) float g_nll[BT_];

__device__ __align__(16) __nv_bfloat16 g_xh [BT_ * C_];
__device__ __align__(16) __nv_bfloat16 g_xl [BT_ * C_];
__device__ __align__(16) __nv_bfloat16 g_ah [BT_ * C_];
__device__ __align__(16) __nv_bfloat16 g_al [BT_ * C_];
__device__ __align__(16) __nv_bfloat16 g_hh [BT_ * C_];
__device__ __align__(16) __nv_bfloat16 g_hl [BT_ * C_];

#define WMAT_ELEMS (C_ * C_)
#define WLM_ROWS   128
#define W_TOTAL    (36 * WMAT_ELEMS + WLM_ROWS * C_)
__device__ __align__(16) __nv_bfloat16 g_wh[W_TOTAL];
__device__ __align__(16) __nv_bfloat16 g_wl[W_TOTAL];
#define WOFF(t, l) ((size_t)((t) * 6 + (l)) * WMAT_ELEMS)
#define WOFF_LM    ((size_t)36 * WMAT_ELEMS)

// ---------------- helpers ----------------
__device__ __forceinline__ uint32_t smem_u32(const void* p) {
    uint32_t a;
    asm("{ .reg .u64 t; cvta.to.shared.u64 t, %1; cvt.u32.u64 %0, t; }"
        : "=r"(a) : "l"(p));
    return a;
}
__device__ __forceinline__ void cp_async16(uint32_t dst, const void* src) {
    asm volatile("cp.async.cg.shared.global [%0], [%1], 16;"
                 :: "r"(dst), "l"(src) : "memory");
}
__device__ __forceinline__ void cp_commit() {
    asm volatile("cp.async.commit_group;" ::: "memory");
}
template <int N>
__device__ __forceinline__ void cp_wait() {
    asm volatile("cp.async.wait_group %0;" :: "n"(N) : "memory");
}
__device__ __forceinline__ void ldmatrix_x4(uint32_t* r, uint32_t addr) {
    asm volatile("ldmatrix.sync.aligned.m8n8.x4.shared.b16 {%0,%1,%2,%3}, [%4];"
                 : "=r"(r[0]), "=r"(r[1]), "=r"(r[2]), "=r"(r[3]) : "r"(addr));
}
__device__ __forceinline__ void mma16816(float* c, const uint32_t* a, const uint32_t* b) {
    asm volatile(
        "mma.sync.aligned.m16n8k16.row.col.f32.bf16.bf16.f32 "
        "{%0,%1,%2,%3}, {%4,%5,%6,%7}, {%8,%9}, {%0,%1,%2,%3};"
        : "+f"(c[0]), "+f"(c[1]), "+f"(c[2]), "+f"(c[3])
        : "r"(a[0]), "r"(a[1]), "r"(a[2]), "r"(a[3]), "r"(b[0]), "r"(b[1]));
}
__device__ __forceinline__ uint32_t packbf2(float a, float b) {
    __nv_bfloat162 t(__float2bfloat16(a), __float2bfloat16(b));
    return *(uint32_t*)&t;
}

// ---------------- merged weight transpose + hi/lo (ALL 37 matrices) --------
__global__ void convw_all(const float* __restrict__ Wq, const float* __restrict__ Wk,
                          const float* __restrict__ Wv, const float* __restrict__ Wo,
                          const float* __restrict__ W1, const float* __restrict__ W2,
                          const float* __restrict__ Wlm,
                          __nv_bfloat16* __restrict__ hi, __nv_bfloat16* __restrict__ lo) {
    const int mat = blockIdx.y;
    const int i = blockIdx.x * 256 + threadIdx.x;
    float v;
    size_t o;
    if (mat < 36) {
        if (i >= WMAT_ELEMS) return;
        const float* srcs[6] = {Wq, Wk, Wv, Wo, W1, W2};
        int t = mat / 6, l = mat % 6;
        const float* s = srcs[t] + (size_t)l * WMAT_ELEMS;
        int n = i >> 8, k = i & 255;
        v = s[(size_t)k * 256 + n];
        o = (size_t)mat * WMAT_ELEMS + i;
    } else {
        if (i >= WLM_ROWS * C_) return;
        int n = i >> 8, k = i & 255;
        v = (n < V_) ? Wlm[(size_t)k * V_ + n] : 0.f;
        o = WOFF_LM + i;
    }
    __nv_bfloat16 h = __float2bfloat16(v);
    hi[o] = h;
    lo[o] = __float2bfloat16(v - __bfloat162float(h));
}

// ---------------- embedding ----------------
__global__ void embed_kernel(const int* __restrict__ idx,
                             const float* __restrict__ tok_emb,
                             const float* __restrict__ pos_emb,
                             float* __restrict__ x,
                             __nv_bfloat16* __restrict__ xh,
                             __nv_bfloat16* __restrict__ xl) {
    int bt = blockIdx.x;
    int c  = threadIdx.x;
    int t  = bt % T_;
    int tok = idx[bt];
    float v = tok_emb[tok * C_ + c] + pos_emb[t * C_ + c];
    size_t o = (size_t)bt * C_ + c;
    x[o] = v;
    __nv_bfloat16 h = __float2bfloat16(v);
    xh[o] = h;
    xl[o] = __float2bfloat16(v - __bfloat162float(h));
}

// ---------------- HMMA GEMM, CTA tile 128 x NT, fused epilogues ------------
template <int NT, int FJ, int MODE>
__global__ void __launch_bounds__(512)
hmma_gemm2(const __nv_bfloat16* __restrict__ Ah, const __nv_bfloat16* __restrict__ Al,
           const __nv_bfloat16* __restrict__ BhBase, const __nv_bfloat16* __restrict__ BlBase,
           size_t wstride, float* outF, size_t ostride,
           __nv_bfloat16* __restrict__ outH, __nv_bfloat16* __restrict__ outL,
           const float* __restrict__ bias, const float* __restrict__ res,
           const float* __restrict__ lnw, const float* __restrict__ lnb, int Nout) {
    extern __shared__ char smem[];
    const uint32_t sb = smem_u32(smem);
    constexpr int STAGE = 16384 + NT * 128;
    constexpr int NCHUNK = 1024 + NT * 8;
    constexpr int WN = NT / 4;

    const int tid  = threadIdx.x;
    const int lane = tid & 31;
    const int w    = tid >> 5;
    const int wm   = w & 3;
    const int wn   = w >> 2;

    const size_t rowblock = (size_t)blockIdx.x * 128;
    const __nv_bfloat16* Bh = BhBase + blockIdx.y * wstride;
    const __nv_bfloat16* Bl = BlBase + blockIdx.y * wstride;
    if (MODE == 0) outF += blockIdx.y * ostride;

    const __nv_bfloat16* Asrc[3] = {Ah, Ah, Al};
    const __nv_bfloat16* Bsrc[3] = {Bh, Bl, Bh};

    float acc[2][FJ][4];
#pragma unroll
    for (int i = 0; i < 2; i++)
#pragma unroll
        for (int j = 0; j < FJ; j++)
#pragma unroll
            for (int r = 0; r < 4; r++) acc[i][j][r] = 0.f;

    auto load_stage = [&](int s, int buf) {
        const int p  = s >> 2;
        const int k0 = (s & 3) * 64;
        const __nv_bfloat16* Ap = Asrc[p];
        const __nv_bfloat16* Bp = Bsrc[p];
        const uint32_t base = sb + buf * STAGE;
#pragma unroll
        for (int c = tid; c < NCHUNK; c += 512) {
            if (c < 1024) {
                int r = c >> 3, h = c & 7;
                cp_async16(base + r * 128 + 16 * (h ^ (r & 7)),
                           Ap + (rowblock + r) * 256 + k0 + h * 8);
            } else {
                int cc = c - 1024;
                int r = cc >> 3, h = cc & 7;
                cp_async16(base + 16384 + r * 128 + 16 * (h ^ (r & 7)),
                           Bp + (size_t)r * 256 + k0 + h * 8);
            }
        }
        cp_commit();
    };

    load_stage(0, 0);

    for (int s = 0; s < 12; s++) {
        if (s < 11) { load_stage(s + 1, (s + 1) & 1); cp_wait<1>(); }
        else        { cp_wait<0>(); }
        __syncthreads();

        const uint32_t base = sb + (s & 1) * STAGE;
#pragma unroll
        for (int ks = 0; ks < 4; ks++) {
            uint32_t a[2][4];
#pragma unroll
            for (int i = 0; i < 2; i++) {
                int r = wm * 32 + i * 16 + (lane & 15);
                int h = 2 * ks + (lane >> 4);
                ldmatrix_x4(a[i], base + r * 128 + 16 * (h ^ (r & 7)));
            }
            uint32_t b[FJ][2];
#pragma unroll
            for (int j2 = 0; j2 < FJ / 2; j2++) {
                int r = wn * WN + j2 * 16 + ((lane >> 4) & 1) * 8 + (lane & 7);
                int h = 2 * ks + ((lane >> 3) & 1);
                uint32_t t4[4];
                ldmatrix_x4(t4, base + 16384 + r * 128 + 16 * (h ^ (r & 7)));
                b[2 * j2][0]     = t4[0];
                b[2 * j2][1]     = t4[1];
                b[2 * j2 + 1][0] = t4[2];
                b[2 * j2 + 1][1] = t4[3];
            }
#pragma unroll
            for (int i = 0; i < 2; i++)
#pragma unroll
                for (int j = 0; j < FJ; j++) mma16816(acc[i][j], a[i], b[j]);
        }
        __syncthreads();
    }

    const int g  = lane >> 2;
    const int tg = lane & 3;

    if (MODE == 0) {
#pragma unroll
        for (int i = 0; i < 2; i++) {
#pragma unroll
            for (int j = 0; j < FJ; j++) {
                int col = wn * WN + j * 8 + tg * 2;
                if (col + 1 >= Nout && col >= Nout) continue;
                size_t r0 = rowblock + wm * 32 + i * 16 + g;
                size_t r1 = r0 + 8;
                float b0 = bias ? bias[col] : 0.f;
                float b1 = bias ? bias[col + 1] : 0.f;
                if (col + 1 < Nout) {
                    *(float2*)(outF + r0 * Nout + col) =
                        make_float2(acc[i][j][0] + b0, acc[i][j][1] + b1);
                    *(float2*)(outF + r1 * Nout + col) =
                        make_float2(acc[i][j][2] + b0, acc[i][j][3] + b1);
                }
            }
        }
    } else if (MODE == 1) {
#pragma unroll
        for (int i = 0; i < 2; i++) {
#pragma unroll
            for (int j = 0; j < FJ; j++) {
                int col = wn * WN + j * 8 + tg * 2;
                size_t r0 = rowblock + wm * 32 + i * 16 + g;
                size_t r1 = r0 + 8;
                float b0 = bias[col], b1 = bias[col + 1];
                float v00 = fmaxf(acc[i][j][0] + b0, 0.f);
                float v01 = fmaxf(acc[i][j][1] + b1, 0.f);
                float v10 = fmaxf(acc[i][j][2] + b0, 0.f);
                float v11 = fmaxf(acc[i][j][3] + b1, 0.f);
                __nv_bfloat16 h00 = __float2bfloat16(v00), h01 = __float2bfloat16(v01);
                __nv_bfloat16 h10 = __float2bfloat16(v10), h11 = __float2bfloat16(v11);
                *(__nv_bfloat162*)(outH + r0 * NT + col) = __nv_bfloat162(h00, h01);
                *(__nv_bfloat162*)(outH + r1 * NT + col) = __nv_bfloat162(h10, h11);
                *(__nv_bfloat162*)(outL + r0 * NT + col) = __nv_bfloat162(
                    __float2bfloat16(v00 - __bfloat162float(h00)),
                    __float2bfloat16(v01 - __bfloat162float(h01)));
                *(__nv_bfloat162*)(outL + r1 * NT + col) = __nv_bfloat162(
                    __float2bfloat16(v10 - __bfloat162float(h10)),
                    __float2bfloat16(v11 - __bfloat162float(h11)));
            }
        }
    } else {
        float* rs = (float*)smem;
        float* rq = rs + 512;
        float vsum[2][2] = {{0.f, 0.f}, {0.f, 0.f}};
        float vsq [2][2] = {{0.f, 0.f}, {0.f, 0.f}};
#pragma unroll
        for (int i = 0; i < 2; i++) {
#pragma unroll
            for (int j = 0; j < FJ; j++) {
                int col = wn * WN + j * 8 + tg * 2;
                size_t r0 = rowblock + wm * 32 + i * 16 + g;
                size_t r1 = r0 + 8;
                float b0 = bias[col], b1 = bias[col + 1];
                float2 q0 = *(const float2*)(res + r0 * NT + col);
                float2 q1 = *(const float2*)(res + r1 * NT + col);
                float v00 = acc[i][j][0] + b0 + q0.x;
                float v01 = acc[i][j][1] + b1 + q0.y;
                float v10 = acc[i][j][2] + b0 + q1.x;
                float v11 = acc[i][j][3] + b1 + q1.y;
                acc[i][j][0] = v00; acc[i][j][1] = v01;
                acc[i][j][2] = v10; acc[i][j][3] = v11;
                vsum[i][0] += v00 + v01;  vsq[i][0] += v00 * v00 + v01 * v01;
                vsum[i][1] += v10 + v11;  vsq[i][1] += v10 * v10 + v11 * v11;
            }
        }
#pragma unroll
        for (int i = 0; i < 2; i++)
#pragma unroll
            for (int hf = 0; hf < 2; hf++) {
                float s = vsum[i][hf], q = vsq[i][hf];
                s += __shfl_xor_sync(0xffffffffu, s, 1);
                s += __shfl_xor_sync(0xffffffffu, s, 2);
                q += __shfl_xor_sync(0xffffffffu, q, 1);
                q += __shfl_xor_sync(0xffffffffu, q, 2);
                if (tg == 0) {
                    int lr = wm * 32 + i * 16 + hf * 8 + g;
                    rs[lr * 4 + wn] = s;
                    rq[lr * 4 + wn] = q;
                }
            }
        __syncthreads();
        float mean[2][2], rstd[2][2];
#pragma unroll
        for (int i = 0; i < 2; i++)
#pragma unroll
            for (int hf = 0; hf < 2; hf++) {
                int lr = wm * 32 + i * 16 + hf * 8 + g;
                float S = rs[lr * 4] + rs[lr * 4 + 1] + rs[lr * 4 + 2] + rs[lr * 4 + 3];
                float Q = rq[lr * 4] + rq[lr * 4 + 1] + rq[lr * 4 + 2] + rq[lr * 4 + 3];
                float mn = S * (1.f / NT);
                float var = Q * (1.f / NT) - mn * mn;
                mean[i][hf] = mn;
                rstd[i][hf] = rsqrtf(var + EPS_);
            }
#pragma unroll
        for (int i = 0; i < 2; i++) {
#pragma unroll
            for (int j = 0; j < FJ; j++) {
                int col = wn * WN + j * 8 + tg * 2;
                size_t r0 = rowblock + wm * 32 + i * 16 + g;
                size_t r1 = r0 + 8;
                float w0 = lnw[col], w1 = lnw[col + 1];
                float c0 = lnb[col], c1 = lnb[col + 1];
                float v00 = (acc[i][j][0] - mean[i][0]) * rstd[i][0] * w0 + c0;
                float v01 = (acc[i][j][1] - mean[i][0]) * rstd[i][0] * w1 + c1;
                float v10 = (acc[i][j][2] - mean[i][1]) * rstd[i][1] * w0 + c0;
                float v11 = (acc[i][j][3] - mean[i][1]) * rstd[i][1] * w1 + c1;
                *(float2*)(outF + r0 * NT + col) = make_float2(v00, v01);
                *(float2*)(outF + r1 * NT + col) = make_float2(v10, v11);
                __nv_bfloat16 h00 = __float2bfloat16(v00), h01 = __float2bfloat16(v01);
                __nv_bfloat16 h10 = __float2bfloat16(v10), h11 = __float2bfloat16(v11);
                *(__nv_bfloat162*)(outH + r0 * NT + col) = __nv_bfloat162(h00, h01);
                *(__nv_bfloat162*)(outH + r1 * NT + col) = __nv_bfloat162(h10, h11);
                *(__nv_bfloat162*)(outL + r0 * NT + col) = __nv_bfloat162(
                    __float2bfloat16(v00 - __bfloat162float(h00)),
                    __float2bfloat16(v01 - __bfloat162float(h01)));
                *(__nv_bfloat162*)(outL + r1 * NT + col) = __nv_bfloat162(
                    __float2bfloat16(v10 - __bfloat162float(h10)),
                    __float2bfloat16(v11 - __bfloat162float(h11)));
            }
        }
    }
}

// ---------------- tensor-core flash attention ----------------
// grid (2 qblocks, B*H), 256 threads = 8 warps x 16 q rows.
// smem: Q hi/lo [128][32] pad-80B rows; K hi/lo [256][32] pad-80B;
//       V^T hi/lo [32][256] pad-528B rows.
#define AQH 0
#define AQL 10240
#define AKH 20480
#define AKL 40960
#define AVH 61440
#define AVL 78336
#define ATTN_SMEM 95232

__global__ void __launch_bounds__(256, 2)
flash_attn(const float* __restrict__ qkv,
           __nv_bfloat16* __restrict__ outH,
           __nv_bfloat16* __restrict__ outL) {
    extern __shared__ char smem[];
    const uint32_t sb = smem_u32(smem);
    const int tid  = threadIdx.x;
    const int lane = tid & 31;
    const int wrow = (tid >> 5) * 16;
    const int g    = lane >> 2;
    const int tg   = lane & 3;
    const int qb   = blockIdx.x;        // 0 or 1
    const int bh   = blockIdx.y;
    const int b    = bh >> 3;
    const int h    = bh & 7;

    const float* qp = qkv + ((size_t)(b * T_ + qb * 128)) * C_ + h * HS_;
    const float* kp = qkv + (size_t)BT_ * C_ + (size_t)(b * T_) * C_ + h * HS_;
    const float* vp = kp + (size_t)BT_ * C_;

    // ---- stage Q (scaled), K, V^T as bf16 hi/lo ----
#pragma unroll
    for (int it = 0; it < 4; it++) {            // Q: 1024 float4
        int i = tid + it * 256;
        int r = i >> 3, c4 = i & 7;
        float4 f = *(const float4*)(qp + (size_t)r * C_ + c4 * 4);
        f.x *= 0.0625f; f.y *= 0.0625f; f.z *= 0.0625f; f.w *= 0.0625f;
        __nv_bfloat16 h0 = __float2bfloat16(f.x), h1 = __float2bfloat16(f.y);
        __nv_bfloat16 h2 = __float2bfloat16(f.z), h3 = __float2bfloat16(f.w);
        uint32_t o = r * 80 + c4 * 8;
        *(__nv_bfloat162*)(smem + AQH + o)     = __nv_bfloat162(h0, h1);
        *(__nv_bfloat162*)(smem + AQH + o + 4) = __nv_bfloat162(h2, h3);
        *(__nv_bfloat162*)(smem + AQL + o)     = __nv_bfloat162(
            __float2bfloat16(f.x - __bfloat162float(h0)),
            __float2bfloat16(f.y - __bfloat162float(h1)));
        *(__nv_bfloat162*)(smem + AQL + o + 4) = __nv_bfloat162(
            __float2bfloat16(f.z - __bfloat162float(h2)),
            __float2bfloat16(f.w - __bfloat162float(h3)));
    }
#pragma unroll
    for (int it = 0; it < 8; it++) {            // K: 2048 float4
        int i = tid + it * 256;
        int r = i >> 3, c4 = i & 7;
        float4 f = *(const float4*)(kp + (size_t)r * C_ + c4 * 4);
        __nv_bfloat16 h0 = __float2bfloat16(f.x), h1 = __float2bfloat16(f.y);
        __nv_bfloat16 h2 = __float2bfloat16(f.z), h3 = __float2bfloat16(f.w);
        uint32_t o = r * 80 + c4 * 8;
        *(__nv_bfloat162*)(smem + AKH + o)     = __nv_bfloat162(h0, h1);
        *(__nv_bfloat162*)(smem + AKH + o + 4) = __nv_bfloat162(h2, h3);
        *(__nv_bfloat162*)(smem + AKL + o)     = __nv_bfloat162(
            __float2bfloat16(f.x - __bfloat162float(h0)),
            __float2bfloat16(f.y - __bfloat162float(h1)));
        *(__nv_bfloat162*)(smem + AKL + o + 4) = __nv_bfloat162(
            __float2bfloat16(f.z - __bfloat162float(h2)),
            __float2bfloat16(f.w - __bfloat162float(h3)));
    }
#pragma unroll
    for (int it = 0; it < 8; it++) {            // V: 2048 float4 -> V^T
        int i = tid + it * 256;
        int r = i >> 3, c4 = i & 7;              // key r, dims 4c4..4c4+3
        float4 f = *(const float4*)(vp + (size_t)r * C_ + c4 * 4);
        float vals[4] = {f.x, f.y, f.z, f.w};
#pragma unroll
        for (int m = 0; m < 4; m++) {
            int d = c4 * 4 + m;
            __nv_bfloat16 hi = __float2bfloat16(vals[m]);
            *(__nv_bfloat16*)(smem + AVH + d * 528 + r * 2) = hi;
            *(__nv_bfloat16*)(smem + AVL + d * 528 + r * 2) =
                __float2bfloat16(vals[m] - __bfloat162float(hi));
        }
    }
    __syncthreads();

    // ---- Q fragments (2 k-steps, hi+lo) ----
    uint32_t qf_h[2][4], qf_l[2][4];
#pragma unroll
    for (int ks = 0; ks < 2; ks++) {
        int r = wrow + (lane & 15);
        int hh = 2 * ks + (lane >> 4);
        ldmatrix_x4(qf_h[ks], sb + AQH + r * 80 + hh * 16);
        ldmatrix_x4(qf_l[ks], sb + AQL + r * 80 + hh * 16);
    }

    float m0 = -INFINITY, m1 = -INFINITY, l0 = 0.f, l1 = 0.f;
    float oacc[4][4];
#pragma unroll
    for (int nd = 0; nd < 4; nd++)
#pragma unroll
        for (int r = 0; r < 4; r++) oacc[nd][r] = 0.f;

    const int nch = (qb == 0) ? 2 : 4;
    const int qrow = qb * 128 + wrow + g;        // row for half 0 (half1 = +8)

    for (int ch = 0; ch < nch; ch++) {
        const int kbase = ch * 64;
        float sacc[8][4];
#pragma unroll
        for (int j = 0; j < 8; j++)
#pragma unroll
            for (int r = 0; r < 4; r++) sacc[j][r] = 0.f;

        // ---- S = Q K^T (3-term) ----
#pragma unroll
        for (int ks = 0; ks < 2; ks++) {
            uint32_t bh_[8][2], bl_[8][2];
#pragma unroll
            for (int j2 = 0; j2 < 4; j2++) {
                int r = kbase + j2 * 16 + ((lane >> 4) & 1) * 8 + (lane & 7);
                int hh = 2 * ks + ((lane >> 3) & 1);
                uint32_t t4[4];
                ldmatrix_x4(t4, sb + AKH + r * 80 + hh * 16);
                bh_[2 * j2][0] = t4[0]; bh_[2 * j2][1] = t4[1];
                bh_[2 * j2 + 1][0] = t4[2]; bh_[2 * j2 + 1][1] = t4[3];
                ldmatrix_x4(t4, sb + AKL + r * 80 + hh * 16);
                bl_[2 * j2][0] = t4[0]; bl_[2 * j2][1] = t4[1];
                bl_[2 * j2 + 1][0] = t4[2]; bl_[2 * j2 + 1][1] = t4[3];
            }
#pragma unroll
            for (int j = 0; j < 8; j++) {
                mma16816(sacc[j], qf_h[ks], bh_[j]);
                mma16816(sacc[j], qf_h[ks], bl_[j]);
                mma16816(sacc[j], qf_l[ks], bh_[j]);
            }
        }

        // ---- causal mask (diagonal chunks only) ----
        if (kbase + 63 > qb * 128 + wrow) {
#pragma unroll
            for (int j = 0; j < 8; j++) {
                int key = kbase + j * 8 + tg * 2;
                if (key     > qrow)     sacc[j][0] = -1e30f;
                if (key + 1 > qrow)     sacc[j][1] = -1e30f;
                if (key     > qrow + 8) sacc[j][2] = -1e30f;
                if (key + 1 > qrow + 8) sacc[j][3] = -1e30f;
            }
        }

        // ---- online softmax ----
        uint32_t ph[8][2], pl[8][2];
        {
            float mx0 = -1e30f, mx1 = -1e30f;
#pragma unroll
            for (int j = 0; j < 8; j++) {
                mx0 = fmaxf(mx0, fmaxf(sacc[j][0], sacc[j][1]));
                mx1 = fmaxf(mx1, fmaxf(sacc[j][2], sacc[j][3]));
            }
            mx0 = fmaxf(mx0, __shfl_xor_sync(0xffffffffu, mx0, 1));
            mx0 = fmaxf(mx0, __shfl_xor_sync(0xffffffffu, mx0, 2));
            mx1 = fmaxf(mx1, __shfl_xor_sync(0xffffffffu, mx1, 1));
            mx1 = fmaxf(mx1, __shfl_xor_sync(0xffffffffu, mx1, 2));
            float mn0 = fmaxf(m0, mx0), mn1 = fmaxf(m1, mx1);
            float cr0 = __expf(m0 - mn0), cr1 = __expf(m1 - mn1);
            float rs0 = 0.f, rs1 = 0.f;
#pragma unroll
            for (int j = 0; j < 8; j++) {
                float p0 = __expf(sacc[j][0] - mn0);
                float p1 = __expf(sacc[j][1] - mn0);
                float p2 = __expf(sacc[j][2] - mn1);
                float p3 = __expf(sacc[j][3] - mn1);
                rs0 += p0 + p1; rs1 += p2 + p3;
                __nv_bfloat16 b0 = __float2bfloat16(p0), b1 = __float2bfloat16(p1);
                __nv_bfloat16 b2 = __float2bfloat16(p2), b3 = __float2bfloat16(p3);
                __nv_bfloat162 t;
                t = __nv_bfloat162(b0, b1); ph[j][0] = *(uint32_t*)&t;
                t = __nv_bfloat162(b2, b3); ph[j][1] = *(uint32_t*)&t;
                pl[j][0] = packbf2(p0 - __bfloat162float(b0), p1 - __bfloat162float(b1));
                pl[j][1] = packbf2(p2 - __bfloat162float(b2), p3 - __bfloat162float(b3));
            }
            rs0 += __shfl_xor_sync(0xffffffffu, rs0, 1);
            rs0 += __shfl_xor_sync(0xffffffffu, rs0, 2);
            rs1 += __shfl_xor_sync(0xffffffffu, rs1, 1);
            rs1 += __shfl_xor_sync(0xffffffffu, rs1, 2);
            l0 = l0 * cr0 + rs0;  l1 = l1 * cr1 + rs1;
            m0 = mn0;  m1 = mn1;
#pragma unroll
            for (int nd = 0; nd < 4; nd++) {
                oacc[nd][0] *= cr0; oacc[nd][1] *= cr0;
                oacc[nd][2] *= cr1; oacc[nd][3] *= cr1;
            }
        }

        // ---- O += P V (3-term) ----
#pragma unroll
        for (int kk = 0; kk < 4; kk++) {
            uint32_t pa_h[4] = {ph[2 * kk][0], ph[2 * kk][1],
                                ph[2 * kk + 1][0], ph[2 * kk + 1][1]};
            uint32_t pa_l[4] = {pl[2 * kk][0], pl[2 * kk][1],
                                pl[2 * kk + 1][0], pl[2 * kk + 1][1]};
            uint32_t vh[4][2], vl[4][2];
#pragma unroll
            for (int nd2 = 0; nd2 < 2; nd2++) {
                int r = nd2 * 16 + ((lane >> 4) & 1) * 8 + (lane & 7);
                int hh = (kbase >> 3) + 2 * kk + ((lane >> 3) & 1);
                uint32_t t4[4];
                ldmatrix_x4(t4, sb + AVH + r * 528 + hh * 16);
                vh[2 * nd2][0] = t4[0]; vh[2 * nd2][1] = t4[1];
                vh[2 * nd2 + 1][0] = t4[2]; vh[2 * nd2 + 1][1] = t4[3];
                ldmatrix_x4(t4, sb + AVL + r * 528 + hh * 16);
                vl[2 * nd2][0] = t4[0]; vl[2 * nd2][1] = t4[1];
                vl[2 * nd2 + 1][0] = t4[2]; vl[2 * nd2 + 1][1] = t4[3];
            }
#pragma unroll
            for (int nd = 0; nd < 4; nd++) {
                mma16816(oacc[nd], pa_h, vh[nd]);
                mma16816(oacc[nd], pa_h, vl[nd]);
                mma16816(oacc[nd], pa_l, vh[nd]);
            }
        }
    }

    // ---- write output ----
    float inv0 = 1.f / l0, inv1 = 1.f / l1;
    size_t r0 = (size_t)(b * T_) + qb * 128 + wrow + g;
    size_t r1 = r0 + 8;
#pragma unroll
    for (int nd = 0; nd < 4; nd++) {
        int col = h * 32 + nd * 8 + tg * 2;
        float v00 = oacc[nd][0] * inv0, v01 = oacc[nd][1] * inv0;
        float v10 = oacc[nd][2] * inv1, v11 = oacc[nd][3] * inv1;
        __nv_bfloat16 h00 = __float2bfloat16(v00), h01 = __float2bfloat16(v01);
        __nv_bfloat16 h10 = __float2bfloat16(v10), h11 = __float2bfloat16(v11);
        *(__nv_bfloat162*)(outH + r0 * C_ + col) = __nv_bfloat162(h00, h01);
        *(__nv_bfloat162*)(outH + r1 * C_ + col) = __nv_bfloat162(h10, h11);
        *(__nv_bfloat162*)(outL + r0 * C_ + col) = __nv_bfloat162(
            __float2bfloat16(v00 - __bfloat162float(h00)),
            __float2bfloat16(v01 - __bfloat162float(h01)));
        *(__nv_bfloat162*)(outL + r1 * C_ + col) = __nv_bfloat162(
            __float2bfloat16(v10 - __bfloat162float(h10)),
            __float2bfloat16(v11 - __bfloat162float(h11)));
    }
}

// ---------------- standalone layernorm (final lnf only) ----------------
__global__ void add_ln_kernel(const float* __restrict__ x,
                              const float* __restrict__ w,
                              const float* __restrict__ b,
                              __nv_bfloat16* __restrict__ outH,
                              __nv_bfloat16* __restrict__ outL) {
    const int row = blockIdx.x;
    const int c = threadIdx.x;
    float v = x[(size_t)row * C_ + c];

    float s = v, s2 = v * v;
    __shared__ float sh1[8], sh2[8];
#pragma unroll
    for (int o = 16; o; o >>= 1) {
        s  += __shfl_xor_sync(0xffffffffu, s, o);
        s2 += __shfl_xor_sync(0xffffffffu, s2, o);
    }
    if ((c & 31) == 0) { sh1[c >> 5] = s; sh2[c >> 5] = s2; }
    __syncthreads();
    if (c < 32) {
        s  = (c < 8) ? sh1[c] : 0.f;
        s2 = (c < 8) ? sh2[c] : 0.f;
#pragma unroll
        for (int o = 4; o; o >>= 1) {
            s  += __shfl_xor_sync(0xffffffffu, s, o);
            s2 += __shfl_xor_sync(0xffffffffu, s2, o);
        }
        if (c == 0) { sh1[0] = s; sh2[0] = s2; }
    }
    __syncthreads();
    float mean = sh1[0] * (1.f / C_);
    float var  = sh2[0] * (1.f / C_) - mean * mean;
    float r = (v - mean) * rsqrtf(var + EPS_) * w[c] + b[c];
    size_t o = (size_t)row * C_ + c;
    __nv_bfloat16 hi = __float2bfloat16(r);
    outH[o] = hi;
    outL[o] = __float2bfloat16(r - __bfloat162float(hi));
}

// ---------------- per-row NLL + loss ----------------
__global__ void nll_kernel(const float* __restrict__ logits,
                           const int* __restrict__ tgt,
                           float* __restrict__ nll) {
    int warp = (blockIdx.x * blockDim.x + threadIdx.x) >> 5;
    int lane = threadIdx.x & 31;
    if (warp >= BT_) return;
    const float* l = logits + (size_t)warp * V_;
    float mx = -INFINITY;
    for (int c = lane; c < V_; c += 32) mx = fmaxf(mx, l[c]);
#pragma unroll
    for (int o = 16; o; o >>= 1) mx = fmaxf(mx, __shfl_xor_sync(0xffffffffu, mx, o));
    float s = 0.f;
    for (int c = lane; c < V_; c += 32) s += __expf(l[c] - mx);
#pragma unroll
    for (int o = 16; o; o >>= 1) s += __shfl_xor_sync(0xffffffffu, s, o);
    if (lane == 0) {
        int t = tgt[warp];
        nll[warp] = -(l[t] - mx - __logf(s));
    }
}

__global__ void reduce_loss_kernel(const float* __restrict__ nll, float* __restrict__ out) {
    __shared__ float sh[256];
    float s = 0.f;
    for (int i = threadIdx.x; i < BT_; i += 256) s += nll[i];
    sh[threadIdx.x] = s;
    __syncthreads();
    for (int st = 128; st; st >>= 1) {
        if (threadIdx.x < st) sh[threadIdx.x] += sh[threadIdx.x + st];
        __syncthreads();
    }
    if (threadIdx.x == 0) *out = sh[0] * (1.f / BT_);
}

// ---------------- host driver ----------------
extern "C" void kernel_launch(void* const* d_in, const int* in_sizes, int n_in,
                              void* d_out, int out_size) {
    const int*   idx     = (const int*)  d_in[0];
    const int*   target  = (const int*)  d_in[1];
    const float* tok_emb = (const float*)d_in[2];
    const float* pos_emb = (const float*)d_in[3];
    const float* Wq      = (const float*)d_in[4];
    const float* Wk      = (const float*)d_in[5];
    const float* Wv      = (const float*)d_in[6];
    const float* Wo      = (const float*)d_in[7];
    const float* bo      = (const float*)d_in[8];
    const float* W1      = (const float*)d_in[9];
    const float* b1      = (const float*)d_in[10];
    const float* W2      = (const float*)d_in[11];
    const float* b2_     = (const float*)d_in[12];
    const float* ln1_w   = (const float*)d_in[13];
    const float* ln1_b   = (const float*)d_in[14];
    const float* ln2_w   = (const float*)d_in[15];
    const float* ln2_b   = (const float*)d_in[16];
    const float* lnf_w   = (const float*)d_in[17];
    const float* lnf_b   = (const float*)d_in[18];
    const float* Wlm     = (const float*)d_in[19];
    const float* blm     = (const float*)d_in[20];

    float *px, *pqkv, *pnll;
    __nv_bfloat16 *pxh, *pxl, *pah, *pal, *phh, *phl, *pwh, *pwl;
    cudaGetSymbolAddress((void**)&px,   g_x);
    cudaGetSymbolAddress((void**)&pqkv, g_qkv);
    cudaGetSymbolAddress((void**)&pnll, g_nll);
    cudaGetSymbolAddress((void**)&pxh,  g_xh);
    cudaGetSymbolAddress((void**)&pxl,  g_xl);
    cudaGetSymbolAddress((void**)&pah,  g_ah);
    cudaGetSymbolAddress((void**)&pal,  g_al);
    cudaGetSymbolAddress((void**)&phh,  g_hh);
    cudaGetSymbolAddress((void**)&phl,  g_hl);
    cudaGetSymbolAddress((void**)&pwh,  g_wh);
    cudaGetSymbolAddress((void**)&pwl,  g_wl);

    cudaFuncSetAttribute(flash_attn, cudaFuncAttributeMaxDynamicSharedMemorySize, ATTN_SMEM);
    const int smem256 = 2 * (16384 + 256 * 128);
    const int smem128 = 2 * (16384 + 128 * 128);
    cudaFuncSetAttribute(hmma_gemm2<256, 8, 0>, cudaFuncAttributeMaxDynamicSharedMemorySize, smem256);
    cudaFuncSetAttribute(hmma_gemm2<256, 8, 1>, cudaFuncAttributeMaxDynamicSharedMemorySize, smem256);
    cudaFuncSetAttribute(hmma_gemm2<256, 8, 2>, cudaFuncAttributeMaxDynamicSharedMemorySize, smem256);
    cudaFuncSetAttribute(hmma_gemm2<128, 4, 0>, cudaFuncAttributeMaxDynamicSharedMemorySize, smem128);

    convw_all<<<dim3(256, 37), 256>>>(Wq, Wk, Wv, Wo, W1, W2, Wlm, pwh, pwl);
    embed_kernel<<<BT_, C_>>>(idx, tok_emb, pos_emb, px, pxh, pxl);

    const size_t QKV_OSTRIDE = (size_t)BT_ * C_;
    const size_t QKV_WSTRIDE = (size_t)6 * WMAT_ELEMS;

    for (int l = 0; l < L_; l++) {
        hmma_gemm2<256, 8, 0><<<dim3(128, 3), 512, smem256>>>(pxh, pxl,
            pwh + WOFF(0, l), pwl + WOFF(0, l), QKV_WSTRIDE,
            pqkv, QKV_OSTRIDE, nullptr, nullptr, nullptr, nullptr, nullptr, nullptr, C_);
        flash_attn<<<dim3(2, B_ * H_), 256, ATTN_SMEM>>>(pqkv, pah, pal);
        hmma_gemm2<256, 8, 2><<<dim3(128, 1), 512, smem256>>>(pah, pal,
            pwh + WOFF(3, l), pwl + WOFF(3, l), 0,
            px, 0, pxh, pxl, bo + l * C_, px, ln1_w + l * C_, ln1_b + l * C_, C_);
        hmma_gemm2<256, 8, 1><<<dim3(128, 1), 512, smem256>>>(pxh, pxl,
            pwh + WOFF(4, l), pwl + WOFF(4, l), 0,
            nullptr, 0, phh, phl, b1 + l * C_, nullptr, nullptr, nullptr, C_);
        hmma_gemm2<256, 8, 2><<<dim3(128, 1), 512, smem256>>>(phh, phl,
            pwh + WOFF(5, l), pwl + WOFF(5, l), 0,
            px, 0, pxh, pxl, b2_ + l * C_, px, ln2_w + l * C_, ln2_b + l * C_, C_);
    }
    add_ln_kernel<<<BT_, C_>>>(px, lnf_w, lnf_b, pxh, pxl);

    float* logits = (out_size >= BT_ * V_) ? (float*)d_out : pqkv;
    hmma_gemm2<128, 4, 0><<<dim3(128, 1), 512, smem128>>>(pxh, pxl,
        pwh + WOFF_LM, pwl + WOFF_LM, 0,
        logits, 0, nullptr, nullptr, blm, nullptr, nullptr, nullptr, V_);

    nll_kernel<<<(BT_ * 32 + 255) / 256, 256>>>(logits, target, pnll);

    float* loss_dst = nullptr;
    if (out_size == 1)              loss_dst = (float*)d_out;
    else if (out_size > BT_ * V_)   loss_dst = (float*)d_out + BT_ * V_;
    if (loss_dst) reduce_loss_kernel<<<1, 256>>>(pnll, loss_dst);
}

// round 6
// speedup vs baseline: 4.8806x; 1.0698x over previous
#include <cuda_runtime.h>
#include <cuda_bf16.h>
#include <cstdint>
#include <math.h>

#define B_  64
#define T_  256
#define C_  256
#define H_  8
#define HS_ 32
#define L_  6
#define V_  96
#define BT_ (B_ * T_)
#define EPS_ 1e-5f

// ---------------- scratch (device globals) ----------------
__device__ __align__(16) float g_x  [BT_ * C_];
__device__ __align__(16) float g_qkv[3 * BT_ * C_];
__device__ __align__(16) float g_nll[BT_];

__device__ __align__(16) __nv_bfloat16 g_xh [BT_ * C_];
__device__ __align__(16) __nv_bfloat16 g_xl [BT_ * C_];
__device__ __align__(16) __nv_bfloat16 g_ah [BT_ * C_];
__device__ __align__(16) __nv_bfloat16 g_al [BT_ * C_];
__device__ __align__(16) __nv_bfloat16 g_hh [BT_ * C_];
__device__ __align__(16) __nv_bfloat16 g_hl [BT_ * C_];

#define WMAT_ELEMS (C_ * C_)
#define WLM_ROWS   128
#define W_TOTAL    (36 * WMAT_ELEMS + WLM_ROWS * C_)
__device__ __align__(16) __nv_bfloat16 g_wh[W_TOTAL];
__device__ __align__(16) __nv_bfloat16 g_wl[W_TOTAL];
#define WOFF(t, l) ((size_t)((t) * 6 + (l)) * WMAT_ELEMS)
#define WOFF_LM    ((size_t)36 * WMAT_ELEMS)

// ---------------- helpers ----------------
__device__ __forceinline__ uint32_t smem_u32(const void* p) {
    uint32_t a;
    asm("{ .reg .u64 t; cvta.to.shared.u64 t, %1; cvt.u32.u64 %0, t; }"
        : "=r"(a) : "l"(p));
    return a;
}
__device__ __forceinline__ void cp_async16(uint32_t dst, const void* src) {
    asm volatile("cp.async.cg.shared.global [%0], [%1], 16;"
                 :: "r"(dst), "l"(src) : "memory");
}
__device__ __forceinline__ void cp_commit() {
    asm volatile("cp.async.commit_group;" ::: "memory");
}
template <int N>
__device__ __forceinline__ void cp_wait() {
    asm volatile("cp.async.wait_group %0;" :: "n"(N) : "memory");
}
__device__ __forceinline__ void ldmatrix_x4(uint32_t* r, uint32_t addr) {
    asm volatile("ldmatrix.sync.aligned.m8n8.x4.shared.b16 {%0,%1,%2,%3}, [%4];"
                 : "=r"(r[0]), "=r"(r[1]), "=r"(r[2]), "=r"(r[3]) : "r"(addr));
}
__device__ __forceinline__ void mma16816(float* c, const uint32_t* a, const uint32_t* b) {
    asm volatile(
        "mma.sync.aligned.m16n8k16.row.col.f32.bf16.bf16.f32 "
        "{%0,%1,%2,%3}, {%4,%5,%6,%7}, {%8,%9}, {%0,%1,%2,%3};"
        : "+f"(c[0]), "+f"(c[1]), "+f"(c[2]), "+f"(c[3])
        : "r"(a[0]), "r"(a[1]), "r"(a[2]), "r"(a[3]), "r"(b[0]), "r"(b[1]));
}
__device__ __forceinline__ uint32_t packbf2(float a, float b) {
    __nv_bfloat162 t(__float2bfloat16(a), __float2bfloat16(b));
    return *(uint32_t*)&t;
}

// ---------------- merged weight transpose + hi/lo (ALL 37 matrices) --------
__global__ void convw_all(const float* __restrict__ Wq, const float* __restrict__ Wk,
                          const float* __restrict__ Wv, const float* __restrict__ Wo,
                          const float* __restrict__ W1, const float* __restrict__ W2,
                          const float* __restrict__ Wlm,
                          __nv_bfloat16* __restrict__ hi, __nv_bfloat16* __restrict__ lo) {
    const int mat = blockIdx.y;
    const int i = blockIdx.x * 256 + threadIdx.x;
    float v;
    size_t o;
    if (mat < 36) {
        if (i >= WMAT_ELEMS) return;
        const float* srcs[6] = {Wq, Wk, Wv, Wo, W1, W2};
        int t = mat / 6, l = mat % 6;
        const float* s = srcs[t] + (size_t)l * WMAT_ELEMS;
        int n = i >> 8, k = i & 255;
        v = s[(size_t)k * 256 + n];
        o = (size_t)mat * WMAT_ELEMS + i;
    } else {
        if (i >= WLM_ROWS * C_) return;
        int n = i >> 8, k = i & 255;
        v = (n < V_) ? Wlm[(size_t)k * V_ + n] : 0.f;
        o = WOFF_LM + i;
    }
    __nv_bfloat16 h = __float2bfloat16(v);
    hi[o] = h;
    lo[o] = __float2bfloat16(v - __bfloat162float(h));
}

// ---------------- embedding ----------------
__global__ void embed_kernel(const int* __restrict__ idx,
                             const float* __restrict__ tok_emb,
                             const float* __restrict__ pos_emb,
                             float* __restrict__ x,
                             __nv_bfloat16* __restrict__ xh,
                             __nv_bfloat16* __restrict__ xl) {
    int bt = blockIdx.x;
    int c  = threadIdx.x;
    int t  = bt % T_;
    int tok = idx[bt];
    float v = tok_emb[tok * C_ + c] + pos_emb[t * C_ + c];
    size_t o = (size_t)bt * C_ + c;
    x[o] = v;
    __nv_bfloat16 h = __float2bfloat16(v);
    xh[o] = h;
    xl[o] = __float2bfloat16(v - __bfloat162float(h));
}

// ---------------- HMMA GEMM v3: co-staged hi/lo, 4 stages, 8 warps 64xWN ---
// out[M,NT] = A[M,256] @ Bt[NT,256]^T, 3-term bf16 split per K-chunk.
// MODE 0: fp32 out (+bias). MODE 1: relu, bf16 hi/lo out.
// MODE 2: +bias +residual -> LayerNorm -> fp32 + bf16 hi/lo out.
template <int NT, int MODE>
__global__ void __launch_bounds__(256)
hmma_gemm3(const __nv_bfloat16* __restrict__ Ah, const __nv_bfloat16* __restrict__ Al,
           const __nv_bfloat16* __restrict__ BhBase, const __nv_bfloat16* __restrict__ BlBase,
           size_t wstride, float* outF, size_t ostride,
           __nv_bfloat16* __restrict__ outH, __nv_bfloat16* __restrict__ outL,
           const float* __restrict__ bias, const float* __restrict__ res,
           const float* __restrict__ lnw, const float* __restrict__ lnb, int Nout) {
    extern __shared__ char smem[];
    const uint32_t sb = smem_u32(smem);
    constexpr int AHo = 0, ALo = 16384, BHo = 32768, BLo = 32768 + NT * 128;
    constexpr int STAGE = 32768 + 2 * NT * 128;
    constexpr int NCH   = 2048 + NT * 16;     // 16B chunks per stage
    constexpr int WN  = NT / 4;               // warp n-width (cols)
    constexpr int FJ  = WN / 8;               // n8 tiles per warp
    constexpr int FJ2 = WN / 16;              // ldmatrix_x4 pairs per warp

    const int tid  = threadIdx.x;
    const int lane = tid & 31;
    const int w    = tid >> 5;
    const int wm   = w & 1;                   // 2 M groups of 64 rows
    const int wn   = w >> 1;                  // 4 N groups of WN cols

    const size_t rowblock = (size_t)blockIdx.x * 128;
    const __nv_bfloat16* Bh = BhBase + blockIdx.y * wstride;
    const __nv_bfloat16* Bl = BlBase + blockIdx.y * wstride;
    if (MODE == 0) outF += blockIdx.y * ostride;

    float acc[4][FJ][4];
#pragma unroll
    for (int i = 0; i < 4; i++)
#pragma unroll
        for (int j = 0; j < FJ; j++)
#pragma unroll
            for (int r = 0; r < 4; r++) acc[i][j][r] = 0.f;

    auto load_stage = [&](int s, int buf) {
        const int k0 = s * 64;
        const uint32_t base = sb + buf * STAGE;
#pragma unroll
        for (int c = tid; c < NCH; c += 256) {
            if (c < 1024) {
                int r = c >> 3, h = c & 7;
                cp_async16(base + AHo + r * 128 + 16 * (h ^ (r & 7)),
                           Ah + (rowblock + r) * 256 + k0 + h * 8);
            } else if (c < 2048) {
                int cc = c - 1024;
                int r = cc >> 3, h = cc & 7;
                cp_async16(base + ALo + r * 128 + 16 * (h ^ (r & 7)),
                           Al + (rowblock + r) * 256 + k0 + h * 8);
            } else if (c < 2048 + NT * 8) {
                int cc = c - 2048;
                int r = cc >> 3, h = cc & 7;
                cp_async16(base + BHo + r * 128 + 16 * (h ^ (r & 7)),
                           Bh + (size_t)r * 256 + k0 + h * 8);
            } else {
                int cc = c - 2048 - NT * 8;
                int r = cc >> 3, h = cc & 7;
                cp_async16(base + BLo + r * 128 + 16 * (h ^ (r & 7)),
                           Bl + (size_t)r * 256 + k0 + h * 8);
            }
        }
        cp_commit();
    };

    load_stage(0, 0);

    for (int s = 0; s < 4; s++) {
        if (s < 3) { load_stage(s + 1, (s + 1) & 1); cp_wait<1>(); }
        else       { cp_wait<0>(); }
        __syncthreads();

        const uint32_t base = sb + (s & 1) * STAGE;
#pragma unroll
        for (int ks = 0; ks < 4; ks++) {
            uint32_t ah[4][4], al[4][4];
#pragma unroll
            for (int i = 0; i < 4; i++) {
                int r = wm * 64 + i * 16 + (lane & 15);
                int hh = 2 * ks + (lane >> 4);
                uint32_t off = r * 128 + 16 * (hh ^ (r & 7));
                ldmatrix_x4(ah[i], base + AHo + off);
                ldmatrix_x4(al[i], base + ALo + off);
            }
#pragma unroll
            for (int j2 = 0; j2 < FJ2; j2++) {
                int r = wn * WN + j2 * 16 + ((lane >> 4) & 1) * 8 + (lane & 7);
                int hh = 2 * ks + ((lane >> 3) & 1);
                uint32_t off = r * 128 + 16 * (hh ^ (r & 7));
                uint32_t bh4[4], bl4[4];
                ldmatrix_x4(bh4, base + BHo + off);
                ldmatrix_x4(bl4, base + BLo + off);
#pragma unroll
                for (int i = 0; i < 4; i++) {
                    mma16816(acc[i][2 * j2],     ah[i], bh4);
                    mma16816(acc[i][2 * j2 + 1], ah[i], bh4 + 2);
                    mma16816(acc[i][2 * j2],     ah[i], bl4);
                    mma16816(acc[i][2 * j2 + 1], ah[i], bl4 + 2);
                    mma16816(acc[i][2 * j2],     al[i], bh4);
                    mma16816(acc[i][2 * j2 + 1], al[i], bh4 + 2);
                }
            }
        }
        __syncthreads();
    }

    const int g  = lane >> 2;
    const int tg = lane & 3;

    if (MODE == 0) {
#pragma unroll
        for (int i = 0; i < 4; i++) {
#pragma unroll
            for (int j = 0; j < FJ; j++) {
                int col = wn * WN + j * 8 + tg * 2;
                if (col >= Nout) continue;
                size_t r0 = rowblock + wm * 64 + i * 16 + g;
                size_t r1 = r0 + 8;
                float b0 = bias ? bias[col] : 0.f;
                float b1 = bias ? bias[col + 1] : 0.f;
                *(float2*)(outF + r0 * Nout + col) =
                    make_float2(acc[i][j][0] + b0, acc[i][j][1] + b1);
                *(float2*)(outF + r1 * Nout + col) =
                    make_float2(acc[i][j][2] + b0, acc[i][j][3] + b1);
            }
        }
    } else if (MODE == 1) {
#pragma unroll
        for (int i = 0; i < 4; i++) {
#pragma unroll
            for (int j = 0; j < FJ; j++) {
                int col = wn * WN + j * 8 + tg * 2;
                size_t r0 = rowblock + wm * 64 + i * 16 + g;
                size_t r1 = r0 + 8;
                float b0 = bias[col], b1 = bias[col + 1];
                float v00 = fmaxf(acc[i][j][0] + b0, 0.f);
                float v01 = fmaxf(acc[i][j][1] + b1, 0.f);
                float v10 = fmaxf(acc[i][j][2] + b0, 0.f);
                float v11 = fmaxf(acc[i][j][3] + b1, 0.f);
                __nv_bfloat16 h00 = __float2bfloat16(v00), h01 = __float2bfloat16(v01);
                __nv_bfloat16 h10 = __float2bfloat16(v10), h11 = __float2bfloat16(v11);
                *(__nv_bfloat162*)(outH + r0 * NT + col) = __nv_bfloat162(h00, h01);
                *(__nv_bfloat162*)(outH + r1 * NT + col) = __nv_bfloat162(h10, h11);
                *(__nv_bfloat162*)(outL + r0 * NT + col) = __nv_bfloat162(
                    __float2bfloat16(v00 - __bfloat162float(h00)),
                    __float2bfloat16(v01 - __bfloat162float(h01)));
                *(__nv_bfloat162*)(outL + r1 * NT + col) = __nv_bfloat162(
                    __float2bfloat16(v10 - __bfloat162float(h10)),
                    __float2bfloat16(v11 - __bfloat162float(h11)));
            }
        }
    } else {
        // MODE 2: v = acc + bias + residual; row LN over NT cols; x + hi/lo out
        float* rs = (float*)smem;             // [128][4]
        float* rq = rs + 512;                 // [128][4]
        float vsum[4][2], vsq[4][2];
#pragma unroll
        for (int i = 0; i < 4; i++) { vsum[i][0] = vsum[i][1] = vsq[i][0] = vsq[i][1] = 0.f; }
#pragma unroll
        for (int i = 0; i < 4; i++) {
#pragma unroll
            for (int j = 0; j < FJ; j++) {
                int col = wn * WN + j * 8 + tg * 2;
                size_t r0 = rowblock + wm * 64 + i * 16 + g;
                size_t r1 = r0 + 8;
                float b0 = bias[col], b1 = bias[col + 1];
                float2 q0 = *(const float2*)(res + r0 * NT + col);
                float2 q1 = *(const float2*)(res + r1 * NT + col);
                float v00 = acc[i][j][0] + b0 + q0.x;
                float v01 = acc[i][j][1] + b1 + q0.y;
                float v10 = acc[i][j][2] + b0 + q1.x;
                float v11 = acc[i][j][3] + b1 + q1.y;
                acc[i][j][0] = v00; acc[i][j][1] = v01;
                acc[i][j][2] = v10; acc[i][j][3] = v11;
                vsum[i][0] += v00 + v01;  vsq[i][0] += v00 * v00 + v01 * v01;
                vsum[i][1] += v10 + v11;  vsq[i][1] += v10 * v10 + v11 * v11;
            }
        }
#pragma unroll
        for (int i = 0; i < 4; i++)
#pragma unroll
            for (int hf = 0; hf < 2; hf++) {
                float s = vsum[i][hf], q = vsq[i][hf];
                s += __shfl_xor_sync(0xffffffffu, s, 1);
                s += __shfl_xor_sync(0xffffffffu, s, 2);
                q += __shfl_xor_sync(0xffffffffu, q, 1);
                q += __shfl_xor_sync(0xffffffffu, q, 2);
                if (tg == 0) {
                    int lr = wm * 64 + i * 16 + hf * 8 + g;
                    rs[lr * 4 + wn] = s;
                    rq[lr * 4 + wn] = q;
                }
            }
        __syncthreads();
        float mean[4][2], rstd[4][2];
#pragma unroll
        for (int i = 0; i < 4; i++)
#pragma unroll
            for (int hf = 0; hf < 2; hf++) {
                int lr = wm * 64 + i * 16 + hf * 8 + g;
                float S = rs[lr * 4] + rs[lr * 4 + 1] + rs[lr * 4 + 2] + rs[lr * 4 + 3];
                float Q = rq[lr * 4] + rq[lr * 4 + 1] + rq[lr * 4 + 2] + rq[lr * 4 + 3];
                float mn = S * (1.f / NT);
                float var = Q * (1.f / NT) - mn * mn;
                mean[i][hf] = mn;
                rstd[i][hf] = rsqrtf(var + EPS_);
            }
#pragma unroll
        for (int i = 0; i < 4; i++) {
#pragma unroll
            for (int j = 0; j < FJ; j++) {
                int col = wn * WN + j * 8 + tg * 2;
                size_t r0 = rowblock + wm * 64 + i * 16 + g;
                size_t r1 = r0 + 8;
                float w0 = lnw[col], w1 = lnw[col + 1];
                float c0 = lnb[col], c1 = lnb[col + 1];
                float v00 = (acc[i][j][0] - mean[i][0]) * rstd[i][0] * w0 + c0;
                float v01 = (acc[i][j][1] - mean[i][0]) * rstd[i][0] * w1 + c1;
                float v10 = (acc[i][j][2] - mean[i][1]) * rstd[i][1] * w0 + c0;
                float v11 = (acc[i][j][3] - mean[i][1]) * rstd[i][1] * w1 + c1;
                *(float2*)(outF + r0 * NT + col) = make_float2(v00, v01);
                *(float2*)(outF + r1 * NT + col) = make_float2(v10, v11);
                __nv_bfloat16 h00 = __float2bfloat16(v00), h01 = __float2bfloat16(v01);
                __nv_bfloat16 h10 = __float2bfloat16(v10), h11 = __float2bfloat16(v11);
                *(__nv_bfloat162*)(outH + r0 * NT + col) = __nv_bfloat162(h00, h01);
                *(__nv_bfloat162*)(outH + r1 * NT + col) = __nv_bfloat162(h10, h11);
                *(__nv_bfloat162*)(outL + r0 * NT + col) = __nv_bfloat162(
                    __float2bfloat16(v00 - __bfloat162float(h00)),
                    __float2bfloat16(v01 - __bfloat162float(h01)));
                *(__nv_bfloat162*)(outL + r1 * NT + col) = __nv_bfloat162(
                    __float2bfloat16(v10 - __bfloat162float(h10)),
                    __float2bfloat16(v11 - __bfloat162float(h11)));
            }
        }
    }
}

// ---------------- tensor-core flash attention (unchanged) ----------------
#define AQH 0
#define AQL 10240
#define AKH 20480
#define AKL 40960
#define AVH 61440
#define AVL 78336
#define ATTN_SMEM 95232

__global__ void __launch_bounds__(256, 2)
flash_attn(const float* __restrict__ qkv,
           __nv_bfloat16* __restrict__ outH,
           __nv_bfloat16* __restrict__ outL) {
    extern __shared__ char smem[];
    const uint32_t sb = smem_u32(smem);
    const int tid  = threadIdx.x;
    const int lane = tid & 31;
    const int wrow = (tid >> 5) * 16;
    const int g    = lane >> 2;
    const int tg   = lane & 3;
    const int qb   = blockIdx.x;
    const int bh   = blockIdx.y;
    const int b    = bh >> 3;
    const int h    = bh & 7;

    const float* qp = qkv + ((size_t)(b * T_ + qb * 128)) * C_ + h * HS_;
    const float* kp = qkv + (size_t)BT_ * C_ + (size_t)(b * T_) * C_ + h * HS_;
    const float* vp = kp + (size_t)BT_ * C_;

#pragma unroll
    for (int it = 0; it < 4; it++) {
        int i = tid + it * 256;
        int r = i >> 3, c4 = i & 7;
        float4 f = *(const float4*)(qp + (size_t)r * C_ + c4 * 4);
        f.x *= 0.0625f; f.y *= 0.0625f; f.z *= 0.0625f; f.w *= 0.0625f;
        __nv_bfloat16 h0 = __float2bfloat16(f.x), h1 = __float2bfloat16(f.y);
        __nv_bfloat16 h2 = __float2bfloat16(f.z), h3 = __float2bfloat16(f.w);
        uint32_t o = r * 80 + c4 * 8;
        *(__nv_bfloat162*)(smem + AQH + o)     = __nv_bfloat162(h0, h1);
        *(__nv_bfloat162*)(smem + AQH + o + 4) = __nv_bfloat162(h2, h3);
        *(__nv_bfloat162*)(smem + AQL + o)     = __nv_bfloat162(
            __float2bfloat16(f.x - __bfloat162float(h0)),
            __float2bfloat16(f.y - __bfloat162float(h1)));
        *(__nv_bfloat162*)(smem + AQL + o + 4) = __nv_bfloat162(
            __float2bfloat16(f.z - __bfloat162float(h2)),
            __float2bfloat16(f.w - __bfloat162float(h3)));
    }
#pragma unroll
    for (int it = 0; it < 8; it++) {
        int i = tid + it * 256;
        int r = i >> 3, c4 = i & 7;
        float4 f = *(const float4*)(kp + (size_t)r * C_ + c4 * 4);
        __nv_bfloat16 h0 = __float2bfloat16(f.x), h1 = __float2bfloat16(f.y);
        __nv_bfloat16 h2 = __float2bfloat16(f.z), h3 = __float2bfloat16(f.w);
        uint32_t o = r * 80 + c4 * 8;
        *(__nv_bfloat162*)(smem + AKH + o)     = __nv_bfloat162(h0, h1);
        *(__nv_bfloat162*)(smem + AKH + o + 4) = __nv_bfloat162(h2, h3);
        *(__nv_bfloat162*)(smem + AKL + o)     = __nv_bfloat162(
            __float2bfloat16(f.x - __bfloat162float(h0)),
            __float2bfloat16(f.y - __bfloat162float(h1)));
        *(__nv_bfloat162*)(smem + AKL + o + 4) = __nv_bfloat162(
            __float2bfloat16(f.z - __bfloat162float(h2)),
            __float2bfloat16(f.w - __bfloat162float(h3)));
    }
#pragma unroll
    for (int it = 0; it < 8; it++) {
        int i = tid + it * 256;
        int r = i >> 3, c4 = i & 7;
        float4 f = *(const float4*)(vp + (size_t)r * C_ + c4 * 4);
        float vals[4] = {f.x, f.y, f.z, f.w};
#pragma unroll
        for (int m = 0; m < 4; m++) {
            int d = c4 * 4 + m;
            __nv_bfloat16 hi = __float2bfloat16(vals[m]);
            *(__nv_bfloat16*)(smem + AVH + d * 528 + r * 2) = hi;
            *(__nv_bfloat16*)(smem + AVL + d * 528 + r * 2) =
                __float2bfloat16(vals[m] - __bfloat162float(hi));
        }
    }
    __syncthreads();

    uint32_t qf_h[2][4], qf_l[2][4];
#pragma unroll
    for (int ks = 0; ks < 2; ks++) {
        int r = wrow + (lane & 15);
        int hh = 2 * ks + (lane >> 4);
        ldmatrix_x4(qf_h[ks], sb + AQH + r * 80 + hh * 16);
        ldmatrix_x4(qf_l[ks], sb + AQL + r * 80 + hh * 16);
    }

    float m0 = -INFINITY, m1 = -INFINITY, l0 = 0.f, l1 = 0.f;
    float oacc[4][4];
#pragma unroll
    for (int nd = 0; nd < 4; nd++)
#pragma unroll
        for (int r = 0; r < 4; r++) oacc[nd][r] = 0.f;

    const int nch = (qb == 0) ? 2 : 4;
    const int qrow = qb * 128 + wrow + g;

    for (int ch = 0; ch < nch; ch++) {
        const int kbase = ch * 64;
        float sacc[8][4];
#pragma unroll
        for (int j = 0; j < 8; j++)
#pragma unroll
            for (int r = 0; r < 4; r++) sacc[j][r] = 0.f;

#pragma unroll
        for (int ks = 0; ks < 2; ks++) {
            uint32_t bh_[8][2], bl_[8][2];
#pragma unroll
            for (int j2 = 0; j2 < 4; j2++) {
                int r = kbase + j2 * 16 + ((lane >> 4) & 1) * 8 + (lane & 7);
                int hh = 2 * ks + ((lane >> 3) & 1);
                uint32_t t4[4];
                ldmatrix_x4(t4, sb + AKH + r * 80 + hh * 16);
                bh_[2 * j2][0] = t4[0]; bh_[2 * j2][1] = t4[1];
                bh_[2 * j2 + 1][0] = t4[2]; bh_[2 * j2 + 1][1] = t4[3];
                ldmatrix_x4(t4, sb + AKL + r * 80 + hh * 16);
                bl_[2 * j2][0] = t4[0]; bl_[2 * j2][1] = t4[1];
                bl_[2 * j2 + 1][0] = t4[2]; bl_[2 * j2 + 1][1] = t4[3];
            }
#pragma unroll
            for (int j = 0; j < 8; j++) {
                mma16816(sacc[j], qf_h[ks], bh_[j]);
                mma16816(sacc[j], qf_h[ks], bl_[j]);
                mma16816(sacc[j], qf_l[ks], bh_[j]);
            }
        }

        if (kbase + 63 > qb * 128 + wrow) {
#pragma unroll
            for (int j = 0; j < 8; j++) {
                int key = kbase + j * 8 + tg * 2;
                if (key     > qrow)     sacc[j][0] = -1e30f;
                if (key + 1 > qrow)     sacc[j][1] = -1e30f;
                if (key     > qrow + 8) sacc[j][2] = -1e30f;
                if (key + 1 > qrow + 8) sacc[j][3] = -1e30f;
            }
        }

        uint32_t ph[8][2], pl[8][2];
        {
            float mx0 = -1e30f, mx1 = -1e30f;
#pragma unroll
            for (int j = 0; j < 8; j++) {
                mx0 = fmaxf(mx0, fmaxf(sacc[j][0], sacc[j][1]));
                mx1 = fmaxf(mx1, fmaxf(sacc[j][2], sacc[j][3]));
            }
            mx0 = fmaxf(mx0, __shfl_xor_sync(0xffffffffu, mx0, 1));
            mx0 = fmaxf(mx0, __shfl_xor_sync(0xffffffffu, mx0, 2));
            mx1 = fmaxf(mx1, __shfl_xor_sync(0xffffffffu, mx1, 1));
            mx1 = fmaxf(mx1, __shfl_xor_sync(0xffffffffu, mx1, 2));
            float mn0 = fmaxf(m0, mx0), mn1 = fmaxf(m1, mx1);
            float cr0 = __expf(m0 - mn0), cr1 = __expf(m1 - mn1);
            float rs0 = 0.f, rs1 = 0.f;
#pragma unroll
            for (int j = 0; j < 8; j++) {
                float p0 = __expf(sacc[j][0] - mn0);
                float p1 = __expf(sacc[j][1] - mn0);
                float p2 = __expf(sacc[j][2] - mn1);
                float p3 = __expf(sacc[j][3] - mn1);
                rs0 += p0 + p1; rs1 += p2 + p3;
                __nv_bfloat16 b0 = __float2bfloat16(p0), b1 = __float2bfloat16(p1);
                __nv_bfloat16 b2 = __float2bfloat16(p2), b3 = __float2bfloat16(p3);
                __nv_bfloat162 t;
                t = __nv_bfloat162(b0, b1); ph[j][0] = *(uint32_t*)&t;
                t = __nv_bfloat162(b2, b3); ph[j][1] = *(uint32_t*)&t;
                pl[j][0] = packbf2(p0 - __bfloat162float(b0), p1 - __bfloat162float(b1));
                pl[j][1] = packbf2(p2 - __bfloat162float(b2), p3 - __bfloat162float(b3));
            }
            rs0 += __shfl_xor_sync(0xffffffffu, rs0, 1);
            rs0 += __shfl_xor_sync(0xffffffffu, rs0, 2);
            rs1 += __shfl_xor_sync(0xffffffffu, rs1, 1);
            rs1 += __shfl_xor_sync(0xffffffffu, rs1, 2);
            l0 = l0 * cr0 + rs0;  l1 = l1 * cr1 + rs1;
            m0 = mn0;  m1 = mn1;
#pragma unroll
            for (int nd = 0; nd < 4; nd++) {
                oacc[nd][0] *= cr0; oacc[nd][1] *= cr0;
                oacc[nd][2] *= cr1; oacc[nd][3] *= cr1;
            }
        }

#pragma unroll
        for (int kk = 0; kk < 4; kk++) {
            uint32_t pa_h[4] = {ph[2 * kk][0], ph[2 * kk][1],
                                ph[2 * kk + 1][0], ph[2 * kk + 1][1]};
            uint32_t pa_l[4] = {pl[2 * kk][0], pl[2 * kk][1],
                                pl[2 * kk + 1][0], pl[2 * kk + 1][1]};
            uint32_t vh[4][2], vl[4][2];
#pragma unroll
            for (int nd2 = 0; nd2 < 2; nd2++) {
                int r = nd2 * 16 + ((lane >> 4) & 1) * 8 + (lane & 7);
                int hh = (kbase >> 3) + 2 * kk + ((lane >> 3) & 1);
                uint32_t t4[4];
                ldmatrix_x4(t4, sb + AVH + r * 528 + hh * 16);
                vh[2 * nd2][0] = t4[0]; vh[2 * nd2][1] = t4[1];
                vh[2 * nd2 + 1][0] = t4[2]; vh[2 * nd2 + 1][1] = t4[3];
                ldmatrix_x4(t4, sb + AVL + r * 528 + hh * 16);
                vl[2 * nd2][0] = t4[0]; vl[2 * nd2][1] = t4[1];
                vl[2 * nd2 + 1][0] = t4[2]; vl[2 * nd2 + 1][1] = t4[3];
            }
#pragma unroll
            for (int nd = 0; nd < 4; nd++) {
                mma16816(oacc[nd], pa_h, vh[nd]);
                mma16816(oacc[nd], pa_h, vl[nd]);
                mma16816(oacc[nd], pa_l, vh[nd]);
            }
        }
    }

    float inv0 = 1.f / l0, inv1 = 1.f / l1;
    size_t r0 = (size_t)(b * T_) + qb * 128 + wrow + g;
    size_t r1 = r0 + 8;
#pragma unroll
    for (int nd = 0; nd < 4; nd++) {
        int col = h * 32 + nd * 8 + tg * 2;
        float v00 = oacc[nd][0] * inv0, v01 = oacc[nd][1] * inv0;
        float v10 = oacc[nd][2] * inv1, v11 = oacc[nd][3] * inv1;
        __nv_bfloat16 h00 = __float2bfloat16(v00), h01 = __float2bfloat16(v01);
        __nv_bfloat16 h10 = __float2bfloat16(v10), h11 = __float2bfloat16(v11);
        *(__nv_bfloat162*)(outH + r0 * C_ + col) = __nv_bfloat162(h00, h01);
        *(__nv_bfloat162*)(outH + r1 * C_ + col) = __nv_bfloat162(h10, h11);
        *(__nv_bfloat162*)(outL + r0 * C_ + col) = __nv_bfloat162(
            __float2bfloat16(v00 - __bfloat162float(h00)),
            __float2bfloat16(v01 - __bfloat162float(h01)));
        *(__nv_bfloat162*)(outL + r1 * C_ + col) = __nv_bfloat162(
            __float2bfloat16(v10 - __bfloat162float(h10)),
            __float2bfloat16(v11 - __bfloat162float(h11)));
    }
}

// ---------------- standalone layernorm (final lnf only) ----------------
__global__ void add_ln_kernel(const float* __restrict__ x,
                              const float* __restrict__ w,
                              const float* __restrict__ b,
                              __nv_bfloat16* __restrict__ outH,
                              __nv_bfloat16* __restrict__ outL) {
    const int row = blockIdx.x;
    const int c = threadIdx.x;
    float v = x[(size_t)row * C_ + c];

    float s = v, s2 = v * v;
    __shared__ float sh1[8], sh2[8];
#pragma unroll
    for (int o = 16; o; o >>= 1) {
        s  += __shfl_xor_sync(0xffffffffu, s, o);
        s2 += __shfl_xor_sync(0xffffffffu, s2, o);
    }
    if ((c & 31) == 0) { sh1[c >> 5] = s; sh2[c >> 5] = s2; }
    __syncthreads();
    if (c < 32) {
        s  = (c < 8) ? sh1[c] : 0.f;
        s2 = (c < 8) ? sh2[c] : 0.f;
#pragma unroll
        for (int o = 4; o; o >>= 1) {
            s  += __shfl_xor_sync(0xffffffffu, s, o);
            s2 += __shfl_xor_sync(0xffffffffu, s2, o);
        }
        if (c == 0) { sh1[0] = s; sh2[0] = s2; }
    }
    __syncthreads();
    float mean = sh1[0] * (1.f / C_);
    float var  = sh2[0] * (1.f / C_) - mean * mean;
    float r = (v - mean) * rsqrtf(var + EPS_) * w[c] + b[c];
    size_t o = (size_t)row * C_ + c;
    __nv_bfloat16 hi = __float2bfloat16(r);
    outH[o] = hi;
    outL[o] = __float2bfloat16(r - __bfloat162float(hi));
}

// ---------------- per-row NLL + loss ----------------
__global__ void nll_kernel(const float* __restrict__ logits,
                           const int* __restrict__ tgt,
                           float* __restrict__ nll) {
    int warp = (blockIdx.x * blockDim.x + threadIdx.x) >> 5;
    int lane = threadIdx.x & 31;
    if (warp >= BT_) return;
    const float* l = logits + (size_t)warp * V_;
    float mx = -INFINITY;
    for (int c = lane; c < V_; c += 32) mx = fmaxf(mx, l[c]);
#pragma unroll
    for (int o = 16; o; o >>= 1) mx = fmaxf(mx, __shfl_xor_sync(0xffffffffu, mx, o));
    float s = 0.f;
    for (int c = lane; c < V_; c += 32) s += __expf(l[c] - mx);
#pragma unroll
    for (int o = 16; o; o >>= 1) s += __shfl_xor_sync(0xffffffffu, s, o);
    if (lane == 0) {
        int t = tgt[warp];
        nll[warp] = -(l[t] - mx - __logf(s));
    }
}

__global__ void reduce_loss_kernel(const float* __restrict__ nll, float* __restrict__ out) {
    __shared__ float sh[256];
    float s = 0.f;
    for (int i = threadIdx.x; i < BT_; i += 256) s += nll[i];
    sh[threadIdx.x] = s;
    __syncthreads();
    for (int st = 128; st; st >>= 1) {
        if (threadIdx.x < st) sh[threadIdx.x] += sh[threadIdx.x + st];
        __syncthreads();
    }
    if (threadIdx.x == 0) *out = sh[0] * (1.f / BT_);
}

// ---------------- host driver ----------------
extern "C" void kernel_launch(void* const* d_in, const int* in_sizes, int n_in,
                              void* d_out, int out_size) {
    const int*   idx     = (const int*)  d_in[0];
    const int*   target  = (const int*)  d_in[1];
    const float* tok_emb = (const float*)d_in[2];
    const float* pos_emb = (const float*)d_in[3];
    const float* Wq      = (const float*)d_in[4];
    const float* Wk      = (const float*)d_in[5];
    const float* Wv      = (const float*)d_in[6];
    const float* Wo      = (const float*)d_in[7];
    const float* bo      = (const float*)d_in[8];
    const float* W1      = (const float*)d_in[9];
    const float* b1      = (const float*)d_in[10];
    const float* W2      = (const float*)d_in[11];
    const float* b2_     = (const float*)d_in[12];
    const float* ln1_w   = (const float*)d_in[13];
    const float* ln1_b   = (const float*)d_in[14];
    const float* ln2_w   = (const float*)d_in[15];
    const float* ln2_b   = (const float*)d_in[16];
    const float* lnf_w   = (const float*)d_in[17];
    const float* lnf_b   = (const float*)d_in[18];
    const float* Wlm     = (const float*)d_in[19];
    const float* blm     = (const float*)d_in[20];

    float *px, *pqkv, *pnll;
    __nv_bfloat16 *pxh, *pxl, *pah, *pal, *phh, *phl, *pwh, *pwl;
    cudaGetSymbolAddress((void**)&px,   g_x);
    cudaGetSymbolAddress((void**)&pqkv, g_qkv);
    cudaGetSymbolAddress((void**)&pnll, g_nll);
    cudaGetSymbolAddress((void**)&pxh,  g_xh);
    cudaGetSymbolAddress((void**)&pxl,  g_xl);
    cudaGetSymbolAddress((void**)&pah,  g_ah);
    cudaGetSymbolAddress((void**)&pal,  g_al);
    cudaGetSymbolAddress((void**)&phh,  g_hh);
    cudaGetSymbolAddress((void**)&phl,  g_hl);
    cudaGetSymbolAddress((void**)&pwh,  g_wh);
    cudaGetSymbolAddress((void**)&pwl,  g_wl);

    cudaFuncSetAttribute(flash_attn, cudaFuncAttributeMaxDynamicSharedMemorySize, ATTN_SMEM);
    const int smem256 = 2 * (32768 + 2 * 256 * 128);   // 196608
    const int smem128 = 2 * (32768 + 2 * 128 * 128);   // 131072
    cudaFuncSetAttribute(hmma_gemm3<256, 0>, cudaFuncAttributeMaxDynamicSharedMemorySize, smem256);
    cudaFuncSetAttribute(hmma_gemm3<256, 1>, cudaFuncAttributeMaxDynamicSharedMemorySize, smem256);
    cudaFuncSetAttribute(hmma_gemm3<256, 2>, cudaFuncAttributeMaxDynamicSharedMemorySize, smem256);
    cudaFuncSetAttribute(hmma_gemm3<128, 0>, cudaFuncAttributeMaxDynamicSharedMemorySize, smem128);

    convw_all<<<dim3(256, 37), 256>>>(Wq, Wk, Wv, Wo, W1, W2, Wlm, pwh, pwl);
    embed_kernel<<<BT_, C_>>>(idx, tok_emb, pos_emb, px, pxh, pxl);

    const size_t QKV_OSTRIDE = (size_t)BT_ * C_;
    const size_t QKV_WSTRIDE = (size_t)6 * WMAT_ELEMS;

    for (int l = 0; l < L_; l++) {
        hmma_gemm3<256, 0><<<dim3(128, 3), 256, smem256>>>(pxh, pxl,
            pwh + WOFF(0, l), pwl + WOFF(0, l), QKV_WSTRIDE,
            pqkv, QKV_OSTRIDE, nullptr, nullptr, nullptr, nullptr, nullptr, nullptr, C_);
        flash_attn<<<dim3(2, B_ * H_), 256, ATTN_SMEM>>>(pqkv, pah, pal);
        hmma_gemm3<256, 2><<<dim3(128, 1), 256, smem256>>>(pah, pal,
            pwh + WOFF(3, l), pwl + WOFF(3, l), 0,
            px, 0, pxh, pxl, bo + l * C_, px, ln1_w + l * C_, ln1_b + l * C_, C_);
        hmma_gemm3<256, 1><<<dim3(128, 1), 256, smem256>>>(pxh, pxl,
            pwh + WOFF(4, l), pwl + WOFF(4, l), 0,
            nullptr, 0, phh, phl, b1 + l * C_, nullptr, nullptr, nullptr, C_);
        hmma_gemm3<256, 2><<<dim3(128, 1), 256, smem256>>>(phh, phl,
            pwh + WOFF(5, l), pwl + WOFF(5, l), 0,
            px, 0, pxh, pxl, b2_ + l * C_, px, ln2_w + l * C_, ln2_b + l * C_, C_);
    }
    add_ln_kernel<<<BT_, C_>>>(px, lnf_w, lnf_b, pxh, pxl);

    float* logits = (out_size >= BT_ * V_) ? (float*)d_out : pqkv;
    hmma_gemm3<128, 0><<<dim3(128, 1), 256, smem128>>>(pxh, pxl,
        pwh + WOFF_LM, pwl + WOFF_LM, 0,
        logits, 0, nullptr, nullptr, blm, nullptr, nullptr, nullptr, V_);

    nll_kernel<<<(BT_ * 32 + 255) / 256, 256>>>(logits, target, pnll);

    float* loss_dst = nullptr;
    if (out_size == 1)              loss_dst = (float*)d_out;
    else if (out_size > BT_ * V_)   loss_dst = (float*)d_out + BT_ * V_;
    if (loss_dst) reduce_loss_kernel<<<1, 256>>>(pnll, loss_dst);
}

// round 7
// speedup vs baseline: 4.8836x; 1.0006x over previous
#include <cuda_runtime.h>
#include <cuda_bf16.h>
#include <cstdint>
#include <math.h>

#define B_  64
#define T_  256
#define C_  256
#define H_  8
#define HS_ 32
#define L_  6
#define V_  96
#define BT_ (B_ * T_)
#define EPS_ 1e-5f

// ---------------- scratch (device globals) ----------------
__device__ __align__(16) float g_x  [BT_ * C_];
__device__ __align__(16) float g_qkv[3 * BT_ * C_];
__device__ __align__(16) float g_nll[BT_];

__device__ __align__(16) __nv_bfloat16 g_xh [BT_ * C_];
__device__ __align__(16) __nv_bfloat16 g_xl [BT_ * C_];
__device__ __align__(16) __nv_bfloat16 g_ah [BT_ * C_];
__device__ __align__(16) __nv_bfloat16 g_al [BT_ * C_];
__device__ __align__(16) __nv_bfloat16 g_hh [BT_ * C_];
__device__ __align__(16) __nv_bfloat16 g_hl [BT_ * C_];

#define WMAT_ELEMS (C_ * C_)
#define WLM_ROWS   128
#define W_TOTAL    (36 * WMAT_ELEMS + WLM_ROWS * C_)
__device__ __align__(16) __nv_bfloat16 g_wh[W_TOTAL];
__device__ __align__(16) __nv_bfloat16 g_wl[W_TOTAL];
#define WOFF(t, l) ((size_t)((t) * 6 + (l)) * WMAT_ELEMS)
#define WOFF_LM    ((size_t)36 * WMAT_ELEMS)

// ---------------- helpers ----------------
__device__ __forceinline__ uint32_t smem_u32(const void* p) {
    uint32_t a;
    asm("{ .reg .u64 t; cvta.to.shared.u64 t, %1; cvt.u32.u64 %0, t; }"
        : "=r"(a) : "l"(p));
    return a;
}
__device__ __forceinline__ void cp_async16(uint32_t dst, const void* src) {
    asm volatile("cp.async.cg.shared.global [%0], [%1], 16;"
                 :: "r"(dst), "l"(src) : "memory");
}
__device__ __forceinline__ void cp_commit() {
    asm volatile("cp.async.commit_group;" ::: "memory");
}
template <int N>
__device__ __forceinline__ void cp_wait() {
    asm volatile("cp.async.wait_group %0;" :: "n"(N) : "memory");
}
__device__ __forceinline__ void ldmatrix_x4(uint32_t* r, uint32_t addr) {
    asm volatile("ldmatrix.sync.aligned.m8n8.x4.shared.b16 {%0,%1,%2,%3}, [%4];"
                 : "=r"(r[0]), "=r"(r[1]), "=r"(r[2]), "=r"(r[3]) : "r"(addr));
}
__device__ __forceinline__ void mma16816(float* c, const uint32_t* a, const uint32_t* b) {
    asm volatile(
        "mma.sync.aligned.m16n8k16.row.col.f32.bf16.bf16.f32 "
        "{%0,%1,%2,%3}, {%4,%5,%6,%7}, {%8,%9}, {%0,%1,%2,%3};"
        : "+f"(c[0]), "+f"(c[1]), "+f"(c[2]), "+f"(c[3])
        : "r"(a[0]), "r"(a[1]), "r"(a[2]), "r"(a[3]), "r"(b[0]), "r"(b[1]));
}
__device__ __forceinline__ uint32_t packbf2(float a, float b) {
    __nv_bfloat162 t(__float2bfloat16(a), __float2bfloat16(b));
    return *(uint32_t*)&t;
}

// ---------------- merged weight transpose + hi/lo (ALL 37 matrices) --------
__global__ void convw_all(const float* __restrict__ Wq, const float* __restrict__ Wk,
                          const float* __restrict__ Wv, const float* __restrict__ Wo,
                          const float* __restrict__ W1, const float* __restrict__ W2,
                          const float* __restrict__ Wlm,
                          __nv_bfloat16* __restrict__ hi, __nv_bfloat16* __restrict__ lo) {
    const int mat = blockIdx.y;
    const int i = blockIdx.x * 256 + threadIdx.x;
    float v;
    size_t o;
    if (mat < 36) {
        if (i >= WMAT_ELEMS) return;
        const float* srcs[6] = {Wq, Wk, Wv, Wo, W1, W2};
        int t = mat / 6, l = mat % 6;
        const float* s = srcs[t] + (size_t)l * WMAT_ELEMS;
        int n = i >> 8, k = i & 255;
        v = s[(size_t)k * 256 + n];
        o = (size_t)mat * WMAT_ELEMS + i;
    } else {
        if (i >= WLM_ROWS * C_) return;
        int n = i >> 8, k = i & 255;
        v = (n < V_) ? Wlm[(size_t)k * V_ + n] : 0.f;
        o = WOFF_LM + i;
    }
    __nv_bfloat16 h = __float2bfloat16(v);
    hi[o] = h;
    lo[o] = __float2bfloat16(v - __bfloat162float(h));
}

// ---------------- embedding ----------------
__global__ void embed_kernel(const int* __restrict__ idx,
                             const float* __restrict__ tok_emb,
                             const float* __restrict__ pos_emb,
                             float* __restrict__ x,
                             __nv_bfloat16* __restrict__ xh,
                             __nv_bfloat16* __restrict__ xl) {
    int bt = blockIdx.x;
    int c  = threadIdx.x;
    int t  = bt % T_;
    int tok = idx[bt];
    float v = tok_emb[tok * C_ + c] + pos_emb[t * C_ + c];
    size_t o = (size_t)bt * C_ + c;
    x[o] = v;
    __nv_bfloat16 h = __float2bfloat16(v);
    xh[o] = h;
    xl[o] = __float2bfloat16(v - __bfloat162float(h));
}

// ---------------- HMMA GEMM v3: co-staged hi/lo, 4 stages, 8 warps 64xWN ---
// out[M,NT] = A[M,256] @ Bt[NT,256]^T, 3-term bf16 split per K-chunk.
// MODE 0: fp32 out (+bias). MODE 1: relu, bf16 hi/lo out.
// MODE 2: +bias +residual -> LayerNorm -> fp32 + bf16 hi/lo out.
template <int NT, int MODE>
__global__ void __launch_bounds__(256)
hmma_gemm3(const __nv_bfloat16* __restrict__ Ah, const __nv_bfloat16* __restrict__ Al,
           const __nv_bfloat16* __restrict__ BhBase, const __nv_bfloat16* __restrict__ BlBase,
           size_t wstride, float* outF, size_t ostride,
           __nv_bfloat16* __restrict__ outH, __nv_bfloat16* __restrict__ outL,
           const float* __restrict__ bias, const float* __restrict__ res,
           const float* __restrict__ lnw, const float* __restrict__ lnb, int Nout) {
    extern __shared__ char smem[];
    const uint32_t sb = smem_u32(smem);
    constexpr int AHo = 0, ALo = 16384, BHo = 32768, BLo = 32768 + NT * 128;
    constexpr int STAGE = 32768 + 2 * NT * 128;
    constexpr int NCH   = 2048 + NT * 16;     // 16B chunks per stage
    constexpr int WN  = NT / 4;               // warp n-width (cols)
    constexpr int FJ  = WN / 8;               // n8 tiles per warp
    constexpr int FJ2 = WN / 16;              // ldmatrix_x4 pairs per warp

    const int tid  = threadIdx.x;
    const int lane = tid & 31;
    const int w    = tid >> 5;
    const int wm   = w & 1;                   // 2 M groups of 64 rows
    const int wn   = w >> 1;                  // 4 N groups of WN cols

    const size_t rowblock = (size_t)blockIdx.x * 128;
    const __nv_bfloat16* Bh = BhBase + blockIdx.y * wstride;
    const __nv_bfloat16* Bl = BlBase + blockIdx.y * wstride;
    if (MODE == 0) outF += blockIdx.y * ostride;

    float acc[4][FJ][4];
#pragma unroll
    for (int i = 0; i < 4; i++)
#pragma unroll
        for (int j = 0; j < FJ; j++)
#pragma unroll
            for (int r = 0; r < 4; r++) acc[i][j][r] = 0.f;

    auto load_stage = [&](int s, int buf) {
        const int k0 = s * 64;
        const uint32_t base = sb + buf * STAGE;
#pragma unroll
        for (int c = tid; c < NCH; c += 256) {
            if (c < 1024) {
                int r = c >> 3, h = c & 7;
                cp_async16(base + AHo + r * 128 + 16 * (h ^ (r & 7)),
                           Ah + (rowblock + r) * 256 + k0 + h * 8);
            } else if (c < 2048) {
                int cc = c - 1024;
                int r = cc >> 3, h = cc & 7;
                cp_async16(base + ALo + r * 128 + 16 * (h ^ (r & 7)),
                           Al + (rowblock + r) * 256 + k0 + h * 8);
            } else if (c < 2048 + NT * 8) {
                int cc = c - 2048;
                int r = cc >> 3, h = cc & 7;
                cp_async16(base + BHo + r * 128 + 16 * (h ^ (r & 7)),
                           Bh + (size_t)r * 256 + k0 + h * 8);
            } else {
                int cc = c - 2048 - NT * 8;
                int r = cc >> 3, h = cc & 7;
                cp_async16(base + BLo + r * 128 + 16 * (h ^ (r & 7)),
                           Bl + (size_t)r * 256 + k0 + h * 8);
            }
        }
        cp_commit();
    };

    load_stage(0, 0);

    for (int s = 0; s < 4; s++) {
        if (s < 3) { load_stage(s + 1, (s + 1) & 1); cp_wait<1>(); }
        else       { cp_wait<0>(); }
        __syncthreads();

        const uint32_t base = sb + (s & 1) * STAGE;
#pragma unroll
        for (int ks = 0; ks < 4; ks++) {
            uint32_t ah[4][4], al[4][4];
#pragma unroll
            for (int i = 0; i < 4; i++) {
                int r = wm * 64 + i * 16 + (lane & 15);
                int hh = 2 * ks + (lane >> 4);
                uint32_t off = r * 128 + 16 * (hh ^ (r & 7));
                ldmatrix_x4(ah[i], base + AHo + off);
                ldmatrix_x4(al[i], base + ALo + off);
            }
#pragma unroll
            for (int j2 = 0; j2 < FJ2; j2++) {
                int r = wn * WN + j2 * 16 + ((lane >> 4) & 1) * 8 + (lane & 7);
                int hh = 2 * ks + ((lane >> 3) & 1);
                uint32_t off = r * 128 + 16 * (hh ^ (r & 7));
                uint32_t bh4[4], bl4[4];
                ldmatrix_x4(bh4, base + BHo + off);
                ldmatrix_x4(bl4, base + BLo + off);
#pragma unroll
                for (int i = 0; i < 4; i++) {
                    mma16816(acc[i][2 * j2],     ah[i], bh4);
                    mma16816(acc[i][2 * j2 + 1], ah[i], bh4 + 2);
                    mma16816(acc[i][2 * j2],     ah[i], bl4);
                    mma16816(acc[i][2 * j2 + 1], ah[i], bl4 + 2);
                    mma16816(acc[i][2 * j2],     al[i], bh4);
                    mma16816(acc[i][2 * j2 + 1], al[i], bh4 + 2);
                }
            }
        }
        __syncthreads();
    }

    const int g  = lane >> 2;
    const int tg = lane & 3;

    if (MODE == 0) {
#pragma unroll
        for (int i = 0; i < 4; i++) {
#pragma unroll
            for (int j = 0; j < FJ; j++) {
                int col = wn * WN + j * 8 + tg * 2;
                if (col >= Nout) continue;
                size_t r0 = rowblock + wm * 64 + i * 16 + g;
                size_t r1 = r0 + 8;
                float b0 = bias ? bias[col] : 0.f;
                float b1 = bias ? bias[col + 1] : 0.f;
                *(float2*)(outF + r0 * Nout + col) =
                    make_float2(acc[i][j][0] + b0, acc[i][j][1] + b1);
                *(float2*)(outF + r1 * Nout + col) =
                    make_float2(acc[i][j][2] + b0, acc[i][j][3] + b1);
            }
        }
    } else if (MODE == 1) {
#pragma unroll
        for (int i = 0; i < 4; i++) {
#pragma unroll
            for (int j = 0; j < FJ; j++) {
                int col = wn * WN + j * 8 + tg * 2;
                size_t r0 = rowblock + wm * 64 + i * 16 + g;
                size_t r1 = r0 + 8;
                float b0 = bias[col], b1 = bias[col + 1];
                float v00 = fmaxf(acc[i][j][0] + b0, 0.f);
                float v01 = fmaxf(acc[i][j][1] + b1, 0.f);
                float v10 = fmaxf(acc[i][j][2] + b0, 0.f);
                float v11 = fmaxf(acc[i][j][3] + b1, 0.f);
                __nv_bfloat16 h00 = __float2bfloat16(v00), h01 = __float2bfloat16(v01);
                __nv_bfloat16 h10 = __float2bfloat16(v10), h11 = __float2bfloat16(v11);
                *(__nv_bfloat162*)(outH + r0 * NT + col) = __nv_bfloat162(h00, h01);
                *(__nv_bfloat162*)(outH + r1 * NT + col) = __nv_bfloat162(h10, h11);
                *(__nv_bfloat162*)(outL + r0 * NT + col) = __nv_bfloat162(
                    __float2bfloat16(v00 - __bfloat162float(h00)),
                    __float2bfloat16(v01 - __bfloat162float(h01)));
                *(__nv_bfloat162*)(outL + r1 * NT + col) = __nv_bfloat162(
                    __float2bfloat16(v10 - __bfloat162float(h10)),
                    __float2bfloat16(v11 - __bfloat162float(h11)));
            }
        }
    } else {
        // MODE 2: v = acc + bias + residual; row LN over NT cols; x + hi/lo out
        float* rs = (float*)smem;             // [128][4]
        float* rq = rs + 512;                 // [128][4]
        float vsum[4][2], vsq[4][2];
#pragma unroll
        for (int i = 0; i < 4; i++) { vsum[i][0] = vsum[i][1] = vsq[i][0] = vsq[i][1] = 0.f; }
#pragma unroll
        for (int i = 0; i < 4; i++) {
#pragma unroll
            for (int j = 0; j < FJ; j++) {
                int col = wn * WN + j * 8 + tg * 2;
                size_t r0 = rowblock + wm * 64 + i * 16 + g;
                size_t r1 = r0 + 8;
                float b0 = bias[col], b1 = bias[col + 1];
                float2 q0 = *(const float2*)(res + r0 * NT + col);
                float2 q1 = *(const float2*)(res + r1 * NT + col);
                float v00 = acc[i][j][0] + b0 + q0.x;
                float v01 = acc[i][j][1] + b1 + q0.y;
                float v10 = acc[i][j][2] + b0 + q1.x;
                float v11 = acc[i][j][3] + b1 + q1.y;
                acc[i][j][0] = v00; acc[i][j][1] = v01;
                acc[i][j][2] = v10; acc[i][j][3] = v11;
                vsum[i][0] += v00 + v01;  vsq[i][0] += v00 * v00 + v01 * v01;
                vsum[i][1] += v10 + v11;  vsq[i][1] += v10 * v10 + v11 * v11;
            }
        }
#pragma unroll
        for (int i = 0; i < 4; i++)
#pragma unroll
            for (int hf = 0; hf < 2; hf++) {
                float s = vsum[i][hf], q = vsq[i][hf];
                s += __shfl_xor_sync(0xffffffffu, s, 1);
                s += __shfl_xor_sync(0xffffffffu, s, 2);
                q += __shfl_xor_sync(0xffffffffu, q, 1);
                q += __shfl_xor_sync(0xffffffffu, q, 2);
                if (tg == 0) {
                    int lr = wm * 64 + i * 16 + hf * 8 + g;
                    rs[lr * 4 + wn] = s;
                    rq[lr * 4 + wn] = q;
                }
            }
        __syncthreads();
        float mean[4][2], rstd[4][2];
#pragma unroll
        for (int i = 0; i < 4; i++)
#pragma unroll
            for (int hf = 0; hf < 2; hf++) {
                int lr = wm * 64 + i * 16 + hf * 8 + g;
                float S = rs[lr * 4] + rs[lr * 4 + 1] + rs[lr * 4 + 2] + rs[lr * 4 + 3];
                float Q = rq[lr * 4] + rq[lr * 4 + 1] + rq[lr * 4 + 2] + rq[lr * 4 + 3];
                float mn = S * (1.f / NT);
                float var = Q * (1.f / NT) - mn * mn;
                mean[i][hf] = mn;
                rstd[i][hf] = rsqrtf(var + EPS_);
            }
#pragma unroll
        for (int i = 0; i < 4; i++) {
#pragma unroll
            for (int j = 0; j < FJ; j++) {
                int col = wn * WN + j * 8 + tg * 2;
                size_t r0 = rowblock + wm * 64 + i * 16 + g;
                size_t r1 = r0 + 8;
                float w0 = lnw[col], w1 = lnw[col + 1];
                float c0 = lnb[col], c1 = lnb[col + 1];
                float v00 = (acc[i][j][0] - mean[i][0]) * rstd[i][0] * w0 + c0;
                float v01 = (acc[i][j][1] - mean[i][0]) * rstd[i][0] * w1 + c1;
                float v10 = (acc[i][j][2] - mean[i][1]) * rstd[i][1] * w0 + c0;
                float v11 = (acc[i][j][3] - mean[i][1]) * rstd[i][1] * w1 + c1;
                *(float2*)(outF + r0 * NT + col) = make_float2(v00, v01);
                *(float2*)(outF + r1 * NT + col) = make_float2(v10, v11);
                __nv_bfloat16 h00 = __float2bfloat16(v00), h01 = __float2bfloat16(v01);
                __nv_bfloat16 h10 = __float2bfloat16(v10), h11 = __float2bfloat16(v11);
                *(__nv_bfloat162*)(outH + r0 * NT + col) = __nv_bfloat162(h00, h01);
                *(__nv_bfloat162*)(outH + r1 * NT + col) = __nv_bfloat162(h10, h11);
                *(__nv_bfloat162*)(outL + r0 * NT + col) = __nv_bfloat162(
                    __float2bfloat16(v00 - __bfloat162float(h00)),
                    __float2bfloat16(v01 - __bfloat162float(h01)));
                *(__nv_bfloat162*)(outL + r1 * NT + col) = __nv_bfloat162(
                    __float2bfloat16(v10 - __bfloat162float(h10)),
                    __float2bfloat16(v11 - __bfloat162float(h11)));
            }
        }
    }
}

// ---------------- tensor-core flash attention (unchanged) ----------------
#define AQH 0
#define AQL 10240
#define AKH 20480
#define AKL 40960
#define AVH 61440
#define AVL 78336
#define ATTN_SMEM 95232

__global__ void __launch_bounds__(256, 2)
flash_attn(const float* __restrict__ qkv,
           __nv_bfloat16* __restrict__ outH,
           __nv_bfloat16* __restrict__ outL) {
    extern __shared__ char smem[];
    const uint32_t sb = smem_u32(smem);
    const int tid  = threadIdx.x;
    const int lane = tid & 31;
    const int wrow = (tid >> 5) * 16;
    const int g    = lane >> 2;
    const int tg   = lane & 3;
    const int qb   = blockIdx.x;
    const int bh   = blockIdx.y;
    const int b    = bh >> 3;
    const int h    = bh & 7;

    const float* qp = qkv + ((size_t)(b * T_ + qb * 128)) * C_ + h * HS_;
    const float* kp = qkv + (size_t)BT_ * C_ + (size_t)(b * T_) * C_ + h * HS_;
    const float* vp = kp + (size_t)BT_ * C_;

#pragma unroll
    for (int it = 0; it < 4; it++) {
        int i = tid + it * 256;
        int r = i >> 3, c4 = i & 7;
        float4 f = *(const float4*)(qp + (size_t)r * C_ + c4 * 4);
        f.x *= 0.0625f; f.y *= 0.0625f; f.z *= 0.0625f; f.w *= 0.0625f;
        __nv_bfloat16 h0 = __float2bfloat16(f.x), h1 = __float2bfloat16(f.y);
        __nv_bfloat16 h2 = __float2bfloat16(f.z), h3 = __float2bfloat16(f.w);
        uint32_t o = r * 80 + c4 * 8;
        *(__nv_bfloat162*)(smem + AQH + o)     = __nv_bfloat162(h0, h1);
        *(__nv_bfloat162*)(smem + AQH + o + 4) = __nv_bfloat162(h2, h3);
        *(__nv_bfloat162*)(smem + AQL + o)     = __nv_bfloat162(
            __float2bfloat16(f.x - __bfloat162float(h0)),
            __float2bfloat16(f.y - __bfloat162float(h1)));
        *(__nv_bfloat162*)(smem + AQL + o + 4) = __nv_bfloat162(
            __float2bfloat16(f.z - __bfloat162float(h2)),
            __float2bfloat16(f.w - __bfloat162float(h3)));
    }
#pragma unroll
    for (int it = 0; it < 8; it++) {
        int i = tid + it * 256;
        int r = i >> 3, c4 = i & 7;
        float4 f = *(const float4*)(kp + (size_t)r * C_ + c4 * 4);
        __nv_bfloat16 h0 = __float2bfloat16(f.x), h1 = __float2bfloat16(f.y);
        __nv_bfloat16 h2 = __float2bfloat16(f.z), h3 = __float2bfloat16(f.w);
        uint32_t o = r * 80 + c4 * 8;
        *(__nv_bfloat162*)(smem + AKH + o)     = __nv_bfloat162(h0, h1);
        *(__nv_bfloat162*)(smem + AKH + o + 4) = __nv_bfloat162(h2, h3);
        *(__nv_bfloat162*)(smem + AKL + o)     = __nv_bfloat162(
            __float2bfloat16(f.x - __bfloat162float(h0)),
            __float2bfloat16(f.y - __bfloat162float(h1)));
        *(__nv_bfloat162*)(smem + AKL + o + 4) = __nv_bfloat162(
            __float2bfloat16(f.z - __bfloat162float(h2)),
            __float2bfloat16(f.w - __bfloat162float(h3)));
    }
#pragma unroll
    for (int it = 0; it < 8; it++) {
        int i = tid + it * 256;
        int r = i >> 3, c4 = i & 7;
        float4 f = *(const float4*)(vp + (size_t)r * C_ + c4 * 4);
        float vals[4] = {f.x, f.y, f.z, f.w};
#pragma unroll
        for (int m = 0; m < 4; m++) {
            int d = c4 * 4 + m;
            __nv_bfloat16 hi = __float2bfloat16(vals[m]);
            *(__nv_bfloat16*)(smem + AVH + d * 528 + r * 2) = hi;
            *(__nv_bfloat16*)(smem + AVL + d * 528 + r * 2) =
                __float2bfloat16(vals[m] - __bfloat162float(hi));
        }
    }
    __syncthreads();

    uint32_t qf_h[2][4], qf_l[2][4];
#pragma unroll
    for (int ks = 0; ks < 2; ks++) {
        int r = wrow + (lane & 15);
        int hh = 2 * ks + (lane >> 4);
        ldmatrix_x4(qf_h[ks], sb + AQH + r * 80 + hh * 16);
        ldmatrix_x4(qf_l[ks], sb + AQL + r * 80 + hh * 16);
    }

    float m0 = -INFINITY, m1 = -INFINITY, l0 = 0.f, l1 = 0.f;
    float oacc[4][4];
#pragma unroll
    for (int nd = 0; nd < 4; nd++)
#pragma unroll
        for (int r = 0; r < 4; r++) oacc[nd][r] = 0.f;

    const int nch = (qb == 0) ? 2 : 4;
    const int qrow = qb * 128 + wrow + g;

    for (int ch = 0; ch < nch; ch++) {
        const int kbase = ch * 64;
        float sacc[8][4];
#pragma unroll
        for (int j = 0; j < 8; j++)
#pragma unroll
            for (int r = 0; r < 4; r++) sacc[j][r] = 0.f;

#pragma unroll
        for (int ks = 0; ks < 2; ks++) {
            uint32_t bh_[8][2], bl_[8][2];
#pragma unroll
            for (int j2 = 0; j2 < 4; j2++) {
                int r = kbase + j2 * 16 + ((lane >> 4) & 1) * 8 + (lane & 7);
                int hh = 2 * ks + ((lane >> 3) & 1);
                uint32_t t4[4];
                ldmatrix_x4(t4, sb + AKH + r * 80 + hh * 16);
                bh_[2 * j2][0] = t4[0]; bh_[2 * j2][1] = t4[1];
                bh_[2 * j2 + 1][0] = t4[2]; bh_[2 * j2 + 1][1] = t4[3];
                ldmatrix_x4(t4, sb + AKL + r * 80 + hh * 16);
                bl_[2 * j2][0] = t4[0]; bl_[2 * j2][1] = t4[1];
                bl_[2 * j2 + 1][0] = t4[2]; bl_[2 * j2 + 1][1] = t4[3];
            }
#pragma unroll
            for (int j = 0; j < 8; j++) {
                mma16816(sacc[j], qf_h[ks], bh_[j]);
                mma16816(sacc[j], qf_h[ks], bl_[j]);
                mma16816(sacc[j], qf_l[ks], bh_[j]);
            }
        }

        if (kbase + 63 > qb * 128 + wrow) {
#pragma unroll
            for (int j = 0; j < 8; j++) {
                int key = kbase + j * 8 + tg * 2;
                if (key     > qrow)     sacc[j][0] = -1e30f;
                if (key + 1 > qrow)     sacc[j][1] = -1e30f;
                if (key     > qrow + 8) sacc[j][2] = -1e30f;
                if (key + 1 > qrow + 8) sacc[j][3] = -1e30f;
            }
        }

        uint32_t ph[8][2], pl[8][2];
        {
            float mx0 = -1e30f, mx1 = -1e30f;
#pragma unroll
            for (int j = 0; j < 8; j++) {
                mx0 = fmaxf(mx0, fmaxf(sacc[j][0], sacc[j][1]));
                mx1 = fmaxf(mx1, fmaxf(sacc[j][2], sacc[j][3]));
            }
            mx0 = fmaxf(mx0, __shfl_xor_sync(0xffffffffu, mx0, 1));
            mx0 = fmaxf(mx0, __shfl_xor_sync(0xffffffffu, mx0, 2));
            mx1 = fmaxf(mx1, __shfl_xor_sync(0xffffffffu, mx1, 1));
            mx1 = fmaxf(mx1, __shfl_xor_sync(0xffffffffu, mx1, 2));
            float mn0 = fmaxf(m0, mx0), mn1 = fmaxf(m1, mx1);
            float cr0 = __expf(m0 - mn0), cr1 = __expf(m1 - mn1);
            float rs0 = 0.f, rs1 = 0.f;
#pragma unroll
            for (int j = 0; j < 8; j++) {
                float p0 = __expf(sacc[j][0] - mn0);
                float p1 = __expf(sacc[j][1] - mn0);
                float p2 = __expf(sacc[j][2] - mn1);
                float p3 = __expf(sacc[j][3] - mn1);
                rs0 += p0 + p1; rs1 += p2 + p3;
                __nv_bfloat16 b0 = __float2bfloat16(p0), b1 = __float2bfloat16(p1);
                __nv_bfloat16 b2 = __float2bfloat16(p2), b3 = __float2bfloat16(p3);
                __nv_bfloat162 t;
                t = __nv_bfloat162(b0, b1); ph[j][0] = *(uint32_t*)&t;
                t = __nv_bfloat162(b2, b3); ph[j][1] = *(uint32_t*)&t;
                pl[j][0] = packbf2(p0 - __bfloat162float(b0), p1 - __bfloat162float(b1));
                pl[j][1] = packbf2(p2 - __bfloat162float(b2), p3 - __bfloat162float(b3));
            }
            rs0 += __shfl_xor_sync(0xffffffffu, rs0, 1);
            rs0 += __shfl_xor_sync(0xffffffffu, rs0, 2);
            rs1 += __shfl_xor_sync(0xffffffffu, rs1, 1);
            rs1 += __shfl_xor_sync(0xffffffffu, rs1, 2);
            l0 = l0 * cr0 + rs0;  l1 = l1 * cr1 + rs1;
            m0 = mn0;  m1 = mn1;
#pragma unroll
            for (int nd = 0; nd < 4; nd++) {
                oacc[nd][0] *= cr0; oacc[nd][1] *= cr0;
                oacc[nd][2] *= cr1; oacc[nd][3] *= cr1;
            }
        }

#pragma unroll
        for (int kk = 0; kk < 4; kk++) {
            uint32_t pa_h[4] = {ph[2 * kk][0], ph[2 * kk][1],
                                ph[2 * kk + 1][0], ph[2 * kk + 1][1]};
            uint32_t pa_l[4] = {pl[2 * kk][0], pl[2 * kk][1],
                                pl[2 * kk + 1][0], pl[2 * kk + 1][1]};
            uint32_t vh[4][2], vl[4][2];
#pragma unroll
            for (int nd2 = 0; nd2 < 2; nd2++) {
                int r = nd2 * 16 + ((lane >> 4) & 1) * 8 + (lane & 7);
                int hh = (kbase >> 3) + 2 * kk + ((lane >> 3) & 1);
                uint32_t t4[4];
                ldmatrix_x4(t4, sb + AVH + r * 528 + hh * 16);
                vh[2 * nd2][0] = t4[0]; vh[2 * nd2][1] = t4[1];
                vh[2 * nd2 + 1][0] = t4[2]; vh[2 * nd2 + 1][1] = t4[3];
                ldmatrix_x4(t4, sb + AVL + r * 528 + hh * 16);
                vl[2 * nd2][0] = t4[0]; vl[2 * nd2][1] = t4[1];
                vl[2 * nd2 + 1][0] = t4[2]; vl[2 * nd2 + 1][1] = t4[3];
            }
#pragma unroll
            for (int nd = 0; nd < 4; nd++) {
                mma16816(oacc[nd], pa_h, vh[nd]);
                mma16816(oacc[nd], pa_h, vl[nd]);
                mma16816(oacc[nd], pa_l, vh[nd]);
            }
        }
    }

    float inv0 = 1.f / l0, inv1 = 1.f / l1;
    size_t r0 = (size_t)(b * T_) + qb * 128 + wrow + g;
    size_t r1 = r0 + 8;
#pragma unroll
    for (int nd = 0; nd < 4; nd++) {
        int col = h * 32 + nd * 8 + tg * 2;
        float v00 = oacc[nd][0] * inv0, v01 = oacc[nd][1] * inv0;
        float v10 = oacc[nd][2] * inv1, v11 = oacc[nd][3] * inv1;
        __nv_bfloat16 h00 = __float2bfloat16(v00), h01 = __float2bfloat16(v01);
        __nv_bfloat16 h10 = __float2bfloat16(v10), h11 = __float2bfloat16(v11);
        *(__nv_bfloat162*)(outH + r0 * C_ + col) = __nv_bfloat162(h00, h01);
        *(__nv_bfloat162*)(outH + r1 * C_ + col) = __nv_bfloat162(h10, h11);
        *(__nv_bfloat162*)(outL + r0 * C_ + col) = __nv_bfloat162(
            __float2bfloat16(v00 - __bfloat162float(h00)),
            __float2bfloat16(v01 - __bfloat162float(h01)));
        *(__nv_bfloat162*)(outL + r1 * C_ + col) = __nv_bfloat162(
            __float2bfloat16(v10 - __bfloat162float(h10)),
            __float2bfloat16(v11 - __bfloat162float(h11)));
    }
}

// ---------------- standalone layernorm (final lnf only) ----------------
__global__ void add_ln_kernel(const float* __restrict__ x,
                              const float* __restrict__ w,
                              const float* __restrict__ b,
                              __nv_bfloat16* __restrict__ outH,
                              __nv_bfloat16* __restrict__ outL) {
    const int row = blockIdx.x;
    const int c = threadIdx.x;
    float v = x[(size_t)row * C_ + c];

    float s = v, s2 = v * v;
    __shared__ float sh1[8], sh2[8];
#pragma unroll
    for (int o = 16; o; o >>= 1) {
        s  += __shfl_xor_sync(0xffffffffu, s, o);
        s2 += __shfl_xor_sync(0xffffffffu, s2, o);
    }
    if ((c & 31) == 0) { sh1[c >> 5] = s; sh2[c >> 5] = s2; }
    __syncthreads();
    if (c < 32) {
        s  = (c < 8) ? sh1[c] : 0.f;
        s2 = (c < 8) ? sh2[c] : 0.f;
#pragma unroll
        for (int o = 4; o; o >>= 1) {
            s  += __shfl_xor_sync(0xffffffffu, s, o);
            s2 += __shfl_xor_sync(0xffffffffu, s2, o);
        }
        if (c == 0) { sh1[0] = s; sh2[0] = s2; }
    }
    __syncthreads();
    float mean = sh1[0] * (1.f / C_);
    float var  = sh2[0] * (1.f / C_) - mean * mean;
    float r = (v - mean) * rsqrtf(var + EPS_) * w[c] + b[c];
    size_t o = (size_t)row * C_ + c;
    __nv_bfloat16 hi = __float2bfloat16(r);
    outH[o] = hi;
    outL[o] = __float2bfloat16(r - __bfloat162float(hi));
}

// ---------------- per-row NLL + loss ----------------
__global__ void nll_kernel(const float* __restrict__ logits,
                           const int* __restrict__ tgt,
                           float* __restrict__ nll) {
    int warp = (blockIdx.x * blockDim.x + threadIdx.x) >> 5;
    int lane = threadIdx.x & 31;
    if (warp >= BT_) return;
    const float* l = logits + (size_t)warp * V_;
    float mx = -INFINITY;
    for (int c = lane; c < V_; c += 32) mx = fmaxf(mx, l[c]);
#pragma unroll
    for (int o = 16; o; o >>= 1) mx = fmaxf(mx, __shfl_xor_sync(0xffffffffu, mx, o));
    float s = 0.f;
    for (int c = lane; c < V_; c += 32) s += __expf(l[c] - mx);
#pragma unroll
    for (int o = 16; o; o >>= 1) s += __shfl_xor_sync(0xffffffffu, s, o);
    if (lane == 0) {
        int t = tgt[warp];
        nll[warp] = -(l[t] - mx - __logf(s));
    }
}

__global__ void reduce_loss_kernel(const float* __restrict__ nll, float* __restrict__ out) {
    __shared__ float sh[256];
    float s = 0.f;
    for (int i = threadIdx.x; i < BT_; i += 256) s += nll[i];
    sh[threadIdx.x] = s;
    __syncthreads();
    for (int st = 128; st; st >>= 1) {
        if (threadIdx.x < st) sh[threadIdx.x] += sh[threadIdx.x + st];
        __syncthreads();
    }
    if (threadIdx.x == 0) *out = sh[0] * (1.f / BT_);
}

// ---------------- host driver ----------------
extern "C" void kernel_launch(void* const* d_in, const int* in_sizes, int n_in,
                              void* d_out, int out_size) {
    const int*   idx     = (const int*)  d_in[0];
    const int*   target  = (const int*)  d_in[1];
    const float* tok_emb = (const float*)d_in[2];
    const float* pos_emb = (const float*)d_in[3];
    const float* Wq      = (const float*)d_in[4];
    const float* Wk      = (const float*)d_in[5];
    const float* Wv      = (const float*)d_in[6];
    const float* Wo      = (const float*)d_in[7];
    const float* bo      = (const float*)d_in[8];
    const float* W1      = (const float*)d_in[9];
    const float* b1      = (const float*)d_in[10];
    const float* W2      = (const float*)d_in[11];
    const float* b2_     = (const float*)d_in[12];
    const float* ln1_w   = (const float*)d_in[13];
    const float* ln1_b   = (const float*)d_in[14];
    const float* ln2_w   = (const float*)d_in[15];
    const float* ln2_b   = (const float*)d_in[16];
    const float* lnf_w   = (const float*)d_in[17];
    const float* lnf_b   = (const float*)d_in[18];
    const float* Wlm     = (const float*)d_in[19];
    const float* blm     = (const float*)d_in[20];

    float *px, *pqkv, *pnll;
    __nv_bfloat16 *pxh, *pxl, *pah, *pal, *phh, *phl, *pwh, *pwl;
    cudaGetSymbolAddress((void**)&px,   g_x);
    cudaGetSymbolAddress((void**)&pqkv, g_qkv);
    cudaGetSymbolAddress((void**)&pnll, g_nll);
    cudaGetSymbolAddress((void**)&pxh,  g_xh);
    cudaGetSymbolAddress((void**)&pxl,  g_xl);
    cudaGetSymbolAddress((void**)&pah,  g_ah);
    cudaGetSymbolAddress((void**)&pal,  g_al);
    cudaGetSymbolAddress((void**)&phh,  g_hh);
    cudaGetSymbolAddress((void**)&phl,  g_hl);
    cudaGetSymbolAddress((void**)&pwh,  g_wh);
    cudaGetSymbolAddress((void**)&pwl,  g_wl);

    cudaFuncSetAttribute(flash_attn, cudaFuncAttributeMaxDynamicSharedMemorySize, ATTN_SMEM);
    const int smem256 = 2 * (32768 + 2 * 256 * 128);   // 196608
    const int smem128 = 2 * (32768 + 2 * 128 * 128);   // 131072
    cudaFuncSetAttribute(hmma_gemm3<256, 0>, cudaFuncAttributeMaxDynamicSharedMemorySize, smem256);
    cudaFuncSetAttribute(hmma_gemm3<256, 1>, cudaFuncAttributeMaxDynamicSharedMemorySize, smem256);
    cudaFuncSetAttribute(hmma_gemm3<256, 2>, cudaFuncAttributeMaxDynamicSharedMemorySize, smem256);
    cudaFuncSetAttribute(hmma_gemm3<128, 0>, cudaFuncAttributeMaxDynamicSharedMemorySize, smem128);

    convw_all<<<dim3(256, 37), 256>>>(Wq, Wk, Wv, Wo, W1, W2, Wlm, pwh, pwl);
    embed_kernel<<<BT_, C_>>>(idx, tok_emb, pos_emb, px, pxh, pxl);

    const size_t QKV_OSTRIDE = (size_t)BT_ * C_;
    const size_t QKV_WSTRIDE = (size_t)6 * WMAT_ELEMS;

    for (int l = 0; l < L_; l++) {
        hmma_gemm3<256, 0><<<dim3(128, 3), 256, smem256>>>(pxh, pxl,
            pwh + WOFF(0, l), pwl + WOFF(0, l), QKV_WSTRIDE,
            pqkv, QKV_OSTRIDE, nullptr, nullptr, nullptr, nullptr, nullptr, nullptr, C_);
        flash_attn<<<dim3(2, B_ * H_), 256, ATTN_SMEM>>>(pqkv, pah, pal);
        hmma_gemm3<256, 2><<<dim3(128, 1), 256, smem256>>>(pah, pal,
            pwh + WOFF(3, l), pwl + WOFF(3, l), 0,
            px, 0, pxh, pxl, bo + l * C_, px, ln1_w + l * C_, ln1_b + l * C_, C_);
        hmma_gemm3<256, 1><<<dim3(128, 1), 256, smem256>>>(pxh, pxl,
            pwh + WOFF(4, l), pwl + WOFF(4, l), 0,
            nullptr, 0, phh, phl, b1 + l * C_, nullptr, nullptr, nullptr, C_);
        hmma_gemm3<256, 2><<<dim3(128, 1), 256, smem256>>>(phh, phl,
            pwh + WOFF(5, l), pwl + WOFF(5, l), 0,
            px, 0, pxh, pxl, b2_ + l * C_, px, ln2_w + l * C_, ln2_b + l * C_, C_);
    }
    add_ln_kernel<<<BT_, C_>>>(px, lnf_w, lnf_b, pxh, pxl);

    float* logits = (out_size >= BT_ * V_) ? (float*)d_out : pqkv;
    hmma_gemm3<128, 0><<<dim3(128, 1), 256, smem128>>>(pxh, pxl,
        pwh + WOFF_LM, pwl + WOFF_LM, 0,
        logits, 0, nullptr, nullptr, blm, nullptr, nullptr, nullptr, V_);

    nll_kernel<<<(BT_ * 32 + 255) / 256, 256>>>(logits, target, pnll);

    float* loss_dst = nullptr;
    if (out_size == 1)              loss_dst = (float*)d_out;
    else if (out_size > BT_ * V_)   loss_dst = (float*)d_out + BT_ * V_;
    if (loss_dst) reduce_loss_kernel<<<1, 256>>>(pnll, loss_dst);
}